// round 1
// baseline (speedup 1.0000x reference)
#include <cuda_runtime.h>

#define NN 122880      // nodes per graph
#define NE 245760      // edges per graph
#define HH 300         // hidden
#define BB 4096        // reactions
#define NODE_IN 64
#define EDGE_IN 16
#define HQ 75          // HH/4 (float4 groups per row)

// ---- scratch (device globals; no allocations allowed) ----
__device__ float g_h [(size_t)NN * HH];
__device__ float g_ef[(size_t)NE * HH];
__device__ float g_z [(size_t)NN * HH];
__device__ float g_t [(size_t)NN * HH];

// ================= GEMM: C = (relu?)(A[M,K] @ W[K,Nc] + bias) =================
#define BM 64
#define BN 64
#define BK 16

__global__ __launch_bounds__(256) void gemm_bias_kernel(
    const float* __restrict__ A, const float* __restrict__ W,
    const float* __restrict__ bias, float* __restrict__ C,
    int M, int K, int Nc, int doRelu)
{
    __shared__ float As[BK][BM];
    __shared__ float Bs[BK][BN];

    const int tid = threadIdx.x;          // 0..255
    const int tx  = tid & 15;             // col group (0..15)
    const int ty  = tid >> 4;             // row group (0..15)
    const int rowBase = blockIdx.y * BM;
    const int colBase = blockIdx.x * BN;

    const int aRow = tid >> 2;            // 0..63
    const int aCol = (tid & 3) << 2;      // 0,4,8,12
    const int wRow = tid >> 4;            // 0..15
    const int wCol = (tid & 15) << 2;     // 0..60

    float acc[4][4];
#pragma unroll
    for (int i = 0; i < 4; i++)
#pragma unroll
        for (int j = 0; j < 4; j++) acc[i][j] = 0.f;

    for (int k0 = 0; k0 < K; k0 += BK) {
        // load A tile (transposed into smem)
        float4 av = make_float4(0.f, 0.f, 0.f, 0.f);
        if (k0 + aCol < K)
            av = *(const float4*)(A + (size_t)(rowBase + aRow) * K + (k0 + aCol));
        As[aCol + 0][aRow] = av.x;
        As[aCol + 1][aRow] = av.y;
        As[aCol + 2][aRow] = av.z;
        As[aCol + 3][aRow] = av.w;

        // load W tile
        float4 wv = make_float4(0.f, 0.f, 0.f, 0.f);
        if ((k0 + wRow) < K && (colBase + wCol) < Nc)
            wv = *(const float4*)(W + (size_t)(k0 + wRow) * Nc + (colBase + wCol));
        *(float4*)&Bs[wRow][wCol] = wv;

        __syncthreads();

#pragma unroll
        for (int k = 0; k < BK; k++) {
            const float4 a = *(const float4*)&As[k][ty << 2];
            const float4 b = *(const float4*)&Bs[k][tx << 2];
            acc[0][0] = fmaf(a.x, b.x, acc[0][0]);
            acc[0][1] = fmaf(a.x, b.y, acc[0][1]);
            acc[0][2] = fmaf(a.x, b.z, acc[0][2]);
            acc[0][3] = fmaf(a.x, b.w, acc[0][3]);
            acc[1][0] = fmaf(a.y, b.x, acc[1][0]);
            acc[1][1] = fmaf(a.y, b.y, acc[1][1]);
            acc[1][2] = fmaf(a.y, b.z, acc[1][2]);
            acc[1][3] = fmaf(a.y, b.w, acc[1][3]);
            acc[2][0] = fmaf(a.z, b.x, acc[2][0]);
            acc[2][1] = fmaf(a.z, b.y, acc[2][1]);
            acc[2][2] = fmaf(a.z, b.z, acc[2][2]);
            acc[2][3] = fmaf(a.z, b.w, acc[2][3]);
            acc[3][0] = fmaf(a.w, b.x, acc[3][0]);
            acc[3][1] = fmaf(a.w, b.y, acc[3][1]);
            acc[3][2] = fmaf(a.w, b.z, acc[3][2]);
            acc[3][3] = fmaf(a.w, b.w, acc[3][3]);
        }
        __syncthreads();
    }

    const int col = colBase + (tx << 2);
    if (col < Nc) {                       // Nc % 4 == 0 -> full float4 valid
        const float4 bv = *(const float4*)(bias + col);
#pragma unroll
        for (int i = 0; i < 4; i++) {
            const int row = rowBase + (ty << 2) + i;
            float4 v;
            v.x = acc[i][0] + bv.x;
            v.y = acc[i][1] + bv.y;
            v.z = acc[i][2] + bv.z;
            v.w = acc[i][3] + bv.w;
            if (doRelu) {
                v.x = fmaxf(v.x, 0.f); v.y = fmaxf(v.y, 0.f);
                v.z = fmaxf(v.z, 0.f); v.w = fmaxf(v.w, 0.f);
            }
            *(float4*)(C + (size_t)row * Nc + col) = v;
        }
    }
}

// ============ message: z[dst] += relu(h[src] + ef), one thread = edge x 4 cols ============
__global__ __launch_bounds__(256) void message_kernel(
    const float* __restrict__ h, const float* __restrict__ ef,
    const int* __restrict__ src, const int* __restrict__ dst,
    float* __restrict__ z)
{
    const int idx = blockIdx.x * blockDim.x + threadIdx.x;
    if (idx >= NE * HQ) return;
    const int e = idx / HQ;
    const int q = (idx - e * HQ) << 2;
    const int s = __ldg(src + e);
    const int d = __ldg(dst + e);
    const float4 hv = *(const float4*)(h + (size_t)s * HH + q);
    const float4 ev = *(const float4*)(ef + (size_t)e * HH + q);
    const float mx = hv.x + ev.x;
    const float my = hv.y + ev.y;
    const float mz = hv.z + ev.z;
    const float mw = hv.w + ev.w;
    float* zp = z + (size_t)d * HH + q;
    if (mx > 0.f) atomicAdd(zp + 0, mx);
    if (my > 0.f) atomicAdd(zp + 1, my);
    if (mz > 0.f) atomicAdd(zp + 2, mz);
    if (mw > 0.f) atomicAdd(zp + 3, mw);
}

// ============ pool: out[seg[n]] += h[n] ============
__global__ __launch_bounds__(256) void pool_kernel(
    const float* __restrict__ h, const int* __restrict__ seg,
    float* __restrict__ out)
{
    const int idx = blockIdx.x * blockDim.x + threadIdx.x;
    if (idx >= NN * HQ) return;
    const int n = idx / HQ;
    const int q = (idx - n * HQ) << 2;
    const int s = __ldg(seg + n);
    const float4 v = *(const float4*)(h + (size_t)n * HH + q);
    float* op = out + (size_t)s * HH + q;
    atomicAdd(op + 0, v.x);
    atomicAdd(op + 1, v.y);
    atomicAdd(op + 2, v.z);
    atomicAdd(op + 3, v.w);
}

__global__ __launch_bounds__(256) void zero_kernel(float* __restrict__ p, int n)
{
    const int idx = blockIdx.x * blockDim.x + threadIdx.x;
    if (idx < n) p[idx] = 0.f;
}

// out[0:BH) = out[BH:2BH) - out[2BH:3BH)
__global__ __launch_bounds__(256) void diff_kernel(float* __restrict__ out)
{
    const int idx = blockIdx.x * blockDim.x + threadIdx.x;
    const int BH = BB * HH;
    if (idx < BH) out[idx] = out[BH + idx] - out[2 * BH + idx];
}

// ============================== host orchestration ==============================
static void run_gin(const float* x, const float* e,
                    const int* src, const int* dst, const int* seg,
                    const float* Wn, const float* bn,
                    const float* We, const float* be,
                    const float* W1, const float* b1,
                    const float* W2, const float* b2,
                    float* h, float* ef, float* z, float* t,
                    float* outPart)
{
    const dim3 gN((HH + BN - 1) / BN, NN / BM);   // (5, 1920)
    const dim3 gE((HH + BN - 1) / BN, NE / BM);   // (5, 3840)

    gemm_bias_kernel<<<gN, 256>>>(x, Wn, bn, h, NN, NODE_IN, HH, 1);
    gemm_bias_kernel<<<gE, 256>>>(e, We, be, ef, NE, EDGE_IN, HH, 0);

    for (int l = 0; l < 3; l++) {
        cudaMemcpyAsync(z, h, (size_t)NN * HH * sizeof(float),
                        cudaMemcpyDeviceToDevice);
        message_kernel<<<(NE * HQ + 255) / 256, 256>>>(h, ef, src, dst, z);
        gemm_bias_kernel<<<gN, 256>>>(z, W1 + (size_t)l * HH * HH, b1 + l * HH,
                                      t, NN, HH, HH, 1);
        gemm_bias_kernel<<<gN, 256>>>(t, W2 + (size_t)l * HH * HH, b2 + l * HH,
                                      h, NN, HH, HH, (l < 2) ? 1 : 0);
    }
    pool_kernel<<<(NN * HQ + 255) / 256, 256>>>(h, seg, outPart);
}

extern "C" void kernel_launch(void* const* d_in, const int* in_sizes, int n_in,
                              void* d_out, int out_size)
{
    const float* r_x = (const float*)d_in[0];
    const float* r_e = (const float*)d_in[1];
    const float* p_x = (const float*)d_in[2];
    const float* p_e = (const float*)d_in[3];
    const float* Wn  = (const float*)d_in[4];
    const float* bn  = (const float*)d_in[5];
    const float* We  = (const float*)d_in[6];
    const float* be  = (const float*)d_in[7];
    const float* W1  = (const float*)d_in[8];
    const float* b1  = (const float*)d_in[9];
    const float* W2  = (const float*)d_in[10];
    const float* b2  = (const float*)d_in[11];
    const int* r_src = (const int*)d_in[12];
    const int* r_dst = (const int*)d_in[13];
    const int* r_seg = (const int*)d_in[14];
    const int* p_src = (const int*)d_in[15];
    const int* p_dst = (const int*)d_in[16];
    const int* p_seg = (const int*)d_in[17];

    float* out   = (float*)d_out;
    float* r_sum = out + (size_t)BB * HH;
    float* p_sum = out + (size_t)2 * BB * HH;

    float *h, *ef, *z, *t;
    cudaGetSymbolAddress((void**)&h,  g_h);
    cudaGetSymbolAddress((void**)&ef, g_ef);
    cudaGetSymbolAddress((void**)&z,  g_z);
    cudaGetSymbolAddress((void**)&t,  g_t);

    // zero accumulation targets (r_sum, p_sum contiguous)
    zero_kernel<<<(2 * BB * HH + 255) / 256, 256>>>(r_sum, 2 * BB * HH);

    for (int g = 0; g < 2; g++) {
        run_gin(r_x + (size_t)g * NN * NODE_IN,
                r_e + (size_t)g * NE * EDGE_IN,
                r_src + (size_t)g * NE, r_dst + (size_t)g * NE,
                r_seg + (size_t)g * NN,
                Wn, bn, We, be, W1, b1, W2, b2,
                h, ef, z, t, r_sum);
    }
    run_gin(p_x, p_e, p_src, p_dst, p_seg,
            Wn, bn, We, be, W1, b1, W2, b2,
            h, ef, z, t, p_sum);

    diff_kernel<<<(BB * HH + 255) / 256, 256>>>(out);
}

// round 4
// speedup vs baseline: 1.3991x; 1.3991x over previous
#include <cuda_runtime.h>
#include <cstdint>

#define NN 122880      // nodes per graph
#define NE 245760      // edges per graph
#define HH 300         // hidden (logical)
#define NP 304         // hidden (padded row stride)
#define BB 4096        // reactions
#define NODE_IN 64
#define EDGE_IN 16

// smem geometry
#define ROWW 36                    // words per smem tile row (32 data + 4 pad)
#define ABUF_BYTES (128 * ROWW * 4)      // 18432
#define BBUF_BYTES (304 * ROWW * 4)      // 43776
#define SMEM_BYTES (2 * ABUF_BYTES + 2 * BBUF_BYTES)  // 124416

// ---- scratch (device globals; no allocations allowed) ----
__device__ float g_h [(size_t)NN * NP];
__device__ float g_ef[(size_t)NE * NP];
__device__ float g_z [(size_t)NN * NP];
__device__ float g_t [(size_t)NN * NP];
__device__ float g_Wnt[(size_t)NP * 64];        // node weights, [n][k], Kp=64
__device__ float g_Wet[(size_t)NP * 32];        // edge weights, [n][k], Kp=32
__device__ float g_W1t[(size_t)3 * NP * 320];   // MLP W1, [n][k], Kp=320
__device__ float g_W2t[(size_t)3 * NP * 320];   // MLP W2, [n][k], Kp=320
__device__ float g_biasp[(size_t)8 * NP];

// ============================ PTX helpers ============================
__device__ __forceinline__ uint32_t smem_u32(const void* p) {
    uint32_t a;
    asm("{ .reg .u64 t; cvta.to.shared.u64 t, %1; cvt.u32.u64 %0, t; }"
        : "=r"(a) : "l"(p));
    return a;
}
__device__ __forceinline__ uint32_t f2tf32(float f) {
    uint32_t u;
    asm("cvt.rna.tf32.f32 %0, %1;" : "=r"(u) : "f"(f));
    return u;
}
// split raw fp32 bits into (hi tf32-exact, lo residual) for 3xTF32
__device__ __forceinline__ void split_tf32(uint32_t raw, uint32_t& hi, uint32_t& lo) {
    const float f = __uint_as_float(raw);
    const uint32_t h = f2tf32(f);
    hi = h;
    lo = __float_as_uint(f - __uint_as_float(h));
}
__device__ __forceinline__ void cp16(uint32_t dst, const void* src, uint32_t sz) {
    asm volatile("cp.async.cg.shared.global [%0], [%1], 16, %2;"
                 :: "r"(dst), "l"(src), "r"(sz) : "memory");
}
#define CP_COMMIT() asm volatile("cp.async.commit_group;" ::: "memory")

#define LDSM4(r, addr) \
    asm volatile("ldmatrix.sync.aligned.m8n8.x4.shared.b16 {%0,%1,%2,%3}, [%4];" \
        : "=r"((r)[0]), "=r"((r)[1]), "=r"((r)[2]), "=r"((r)[3]) : "r"(addr))
#define LDSM2(r, addr) \
    asm volatile("ldmatrix.sync.aligned.m8n8.x2.shared.b16 {%0,%1}, [%2];" \
        : "=r"((r)[0]), "=r"((r)[1]) : "r"(addr))

#define MMA(d, a, bb0, bb1) \
    asm volatile("mma.sync.aligned.m16n8k8.row.col.f32.tf32.tf32.f32 " \
        "{%0,%1,%2,%3}, {%4,%5,%6,%7}, {%8,%9}, {%0,%1,%2,%3};" \
        : "+f"((d)[0]), "+f"((d)[1]), "+f"((d)[2]), "+f"((d)[3]) \
        : "r"((a)[0]), "r"((a)[1]), "r"((a)[2]), "r"((a)[3]), \
          "r"(bb0), "r"(bb1))

// 3xTF32 compensated product: d += a*b with near-fp32 precision
#define MMA3(d, ah, al, bh0, bh1, bl0, bl1) do { \
    MMA(d, al, bh0, bh1); \
    MMA(d, ah, bl0, bl1); \
    MMA(d, ah, bh0, bh1); \
} while (0)

// ============================ tensor-core 3xTF32 GEMM ============================
// C[M, NP] = (relu?)(A[M, Kact] @ W[Kact, 300->NP]), weights prepacked as Wt[n][Kp] (raw fp32)
// grid.x = M/128, block = 256 (8 warps: 4 m-quarters x 2 n-halves)
__global__ __launch_bounds__(256, 1) void gemm_tc(
    const float* __restrict__ A, const float* __restrict__ Wt,
    const float* __restrict__ biasp, float* __restrict__ C,
    float* __restrict__ C2, int lda, int Kact, int Kp, int kchunks, int doRelu)
{
    extern __shared__ char smem[];
    const uint32_t sb = smem_u32(smem);
    const int tid  = threadIdx.x;
    const int wid  = tid >> 5;
    const int lane = tid & 31;
    const int wm   = wid & 3;          // m quarter (32 rows)
    const int wn   = wid >> 2;         // n half (152 cols)
    const size_t rowBase = (size_t)blockIdx.x * 128;

    const uint32_t Abase[2] = { sb, sb + ABUF_BYTES };
    const uint32_t Bbase[2] = { sb + 2 * ABUF_BYTES, sb + 2 * ABUF_BYTES + BBUF_BYTES };

    // ldmatrix per-lane byte offsets
    const int lrow = lane & 15;
    const int lkh  = (lane >> 4) & 1;
    const uint32_t aoff0 = ((uint32_t)(wm * 32 + lrow) * ROWW + lkh * 4) * 4;
    const uint32_t aoff1 = aoff0 + 16 * ROWW * 4;
    const uint32_t boff  = ((uint32_t)(wn * 152 + (lane & 7) + ((lane >> 4) & 1) * 8) * ROWW
                            + ((lane >> 3) & 1) * 4) * 4;
    const uint32_t boff2 = ((uint32_t)(wn * 152 + 144 + (lane & 7)) * ROWW
                            + ((lane >> 3) & 1) * 4) * 4;

    float acc[2][19][4];
#pragma unroll
    for (int i = 0; i < 2; i++)
#pragma unroll
        for (int j = 0; j < 19; j++)
#pragma unroll
            for (int q = 0; q < 4; q++) acc[i][j][q] = 0.f;

    // ---------- tile fill (cp.async) ----------
    auto fill = [&](int cidx) {
        const int b = cidx & 1;
        const int k0 = cidx * 32;
        // A: 128 rows x 32k, tasks = 128*8 float4
#pragma unroll
        for (int i = 0; i < 4; ++i) {
            const int flat = tid + (i << 8);
            const int r = flat >> 3;
            const int j = flat & 7;
            const int k = k0 + (j << 2);
            const uint32_t dst = Abase[b] + (uint32_t)r * (ROWW * 4) + j * 16;
            const float* src = A + (rowBase + r) * lda + k;
            cp16(dst, (k < Kact) ? src : A, (k < Kact) ? 16u : 0u);
        }
        // B: 304 n-rows x 32k, tasks = 304*8 float4
#pragma unroll
        for (int i = 0; i < 10; ++i) {
            const int flat = tid + (i << 8);
            if (flat < 304 * 8) {
                const int n = flat >> 3;
                const int j = flat & 7;
                const uint32_t dst = Bbase[b] + (uint32_t)n * (ROWW * 4) + j * 16;
                cp16(dst, Wt + (size_t)n * Kp + k0 + (j << 2), 16u);
            }
        }
        CP_COMMIT();
    };

    fill(0);
    if (kchunks > 1) fill(1);

    for (int c = 0; c < kchunks; ++c) {
        if (c + 1 < kchunks) asm volatile("cp.async.wait_group 1;" ::: "memory");
        else                 asm volatile("cp.async.wait_group 0;" ::: "memory");
        __syncthreads();

        const uint32_t Acur = Abase[c & 1];
        const uint32_t Bcur = Bbase[c & 1];
#pragma unroll
        for (int ks = 0; ks < 4; ++ks) {
            uint32_t a0[4], a1[4];
            const uint32_t ab = Acur + ks * 32;
            LDSM4(a0, ab + aoff0);
            LDSM4(a1, ab + aoff1);
            uint32_t a0h[4], a0l[4], a1h[4], a1l[4];
#pragma unroll
            for (int q = 0; q < 4; ++q) {
                split_tf32(a0[q], a0h[q], a0l[q]);
                split_tf32(a1[q], a1h[q], a1l[q]);
            }
            const uint32_t bb = Bcur + ks * 32;
#pragma unroll
            for (int ntp = 0; ntp < 9; ++ntp) {
                uint32_t bf[4], bh[4], bl[4];
                LDSM4(bf, bb + boff + (uint32_t)ntp * (16 * ROWW * 4));
#pragma unroll
                for (int q = 0; q < 4; ++q) split_tf32(bf[q], bh[q], bl[q]);
                MMA3(acc[0][2 * ntp],     a0h, a0l, bh[0], bh[1], bl[0], bl[1]);
                MMA3(acc[1][2 * ntp],     a1h, a1l, bh[0], bh[1], bl[0], bl[1]);
                MMA3(acc[0][2 * ntp + 1], a0h, a0l, bh[2], bh[3], bl[2], bl[3]);
                MMA3(acc[1][2 * ntp + 1], a1h, a1l, bh[2], bh[3], bl[2], bl[3]);
            }
            uint32_t b2[2], b2h[2], b2l[2];
            LDSM2(b2, bb + boff2);
            split_tf32(b2[0], b2h[0], b2l[0]);
            split_tf32(b2[1], b2h[1], b2l[1]);
            MMA3(acc[0][18], a0h, a0l, b2h[0], b2h[1], b2l[0], b2l[1]);
            MMA3(acc[1][18], a1h, a1l, b2h[0], b2h[1], b2l[0], b2l[1]);
        }
        __syncthreads();
        if (c + 2 < kchunks) fill(c + 2);
    }

    // ---------- epilogue: bias + relu, direct float2 stores ----------
    const int colq = (lane & 3) * 2;
    const int rquad = lane >> 2;
#pragma unroll
    for (int mt = 0; mt < 2; ++mt) {
        const size_t row0 = rowBase + wm * 32 + mt * 16 + rquad;
#pragma unroll
        for (int nt = 0; nt < 19; ++nt) {
            const int col = wn * 152 + nt * 8 + colq;
            const float2 bv = *(const float2*)(biasp + col);
            float2 v01, v23;
            v01.x = acc[mt][nt][0] + bv.x;
            v01.y = acc[mt][nt][1] + bv.y;
            v23.x = acc[mt][nt][2] + bv.x;
            v23.y = acc[mt][nt][3] + bv.y;
            if (doRelu) {
                v01.x = fmaxf(v01.x, 0.f); v01.y = fmaxf(v01.y, 0.f);
                v23.x = fmaxf(v23.x, 0.f); v23.y = fmaxf(v23.y, 0.f);
            }
            const size_t o0 = row0 * NP + col;
            const size_t o1 = (row0 + 8) * NP + col;
            *(float2*)(C + o0) = v01;
            *(float2*)(C + o1) = v23;
            if (C2) {
                *(float2*)(C2 + o0) = v01;
                *(float2*)(C2 + o1) = v23;
            }
        }
    }
}

// ============ prepack: transpose + pad weights (raw fp32) ============
// W[Kin][300] row-major -> Wt[NP][Kp] (n-major rows of k), zero padded
__global__ __launch_bounds__(256) void pack_wt_kernel(
    const float* __restrict__ W, float* __restrict__ Wt, int Kin, int Kp)
{
    const int idx = blockIdx.x * 256 + threadIdx.x;
    if (idx >= NP * Kp) return;
    const int n = idx / Kp;
    const int k = idx - n * Kp;
    float v = 0.f;
    if (k < Kin && n < HH) v = W[(size_t)k * HH + n];
    Wt[idx] = v;
}
__global__ void pad_bias_kernel(const float* __restrict__ in, float* __restrict__ out)
{
    const int n = threadIdx.x;
    if (n < NP) out[n] = (n < HH) ? in[n] : 0.f;
}

// ============ message: z[dst] += relu(h[src] + ef), thread = edge x 8 cols ============
__global__ __launch_bounds__(256) void message_kernel(
    const float* __restrict__ h, const float* __restrict__ ef,
    const int* __restrict__ src, const int* __restrict__ dst,
    float* __restrict__ z)
{
    const int idx = blockIdx.x * blockDim.x + threadIdx.x;
    if (idx >= NE * 38) return;
    const int e = idx / 38;
    const int q = (idx - e * 38) << 3;
    const int s = __ldg(src + e);
    const int d = __ldg(dst + e);
    const float4* hp = (const float4*)(h + (size_t)s * NP + q);
    const float4* ep = (const float4*)(ef + (size_t)e * NP + q);
    const float4 h0 = hp[0], h1 = hp[1];
    const float4 e0 = ep[0], e1 = ep[1];
    float* zp = z + (size_t)d * NP + q;
    float m;
    m = h0.x + e0.x; if (m > 0.f) atomicAdd(zp + 0, m);
    m = h0.y + e0.y; if (m > 0.f) atomicAdd(zp + 1, m);
    m = h0.z + e0.z; if (m > 0.f) atomicAdd(zp + 2, m);
    m = h0.w + e0.w; if (m > 0.f) atomicAdd(zp + 3, m);
    m = h1.x + e1.x; if (m > 0.f) atomicAdd(zp + 4, m);
    m = h1.y + e1.y; if (m > 0.f) atomicAdd(zp + 5, m);
    m = h1.z + e1.z; if (m > 0.f) atomicAdd(zp + 6, m);
    m = h1.w + e1.w; if (m > 0.f) atomicAdd(zp + 7, m);
}

// ============ pool: out[seg[n]] += h[n] (300 cols) ============
__global__ __launch_bounds__(256) void pool_kernel(
    const float* __restrict__ h, const int* __restrict__ seg,
    float* __restrict__ out)
{
    const int idx = blockIdx.x * blockDim.x + threadIdx.x;
    if (idx >= NN * 75) return;
    const int n = idx / 75;
    const int q = (idx - n * 75) << 2;
    const int s = __ldg(seg + n);
    const float4 v = *(const float4*)(h + (size_t)n * NP + q);
    float* op = out + (size_t)s * HH + q;
    atomicAdd(op + 0, v.x);
    atomicAdd(op + 1, v.y);
    atomicAdd(op + 2, v.z);
    atomicAdd(op + 3, v.w);
}

__global__ __launch_bounds__(256) void zero_kernel(float* __restrict__ p, int n)
{
    const int idx = blockIdx.x * blockDim.x + threadIdx.x;
    if (idx < n) p[idx] = 0.f;
}

__global__ __launch_bounds__(256) void diff_kernel(float* __restrict__ out)
{
    const int idx = blockIdx.x * blockDim.x + threadIdx.x;
    const int BH = BB * HH;
    if (idx < BH) out[idx] = out[BH + idx] - out[2 * BH + idx];
}

// ============================== host orchestration ==============================
static void run_gin(const float* x, const float* e,
                    const int* src, const int* dst, const int* seg,
                    float* Wnt, float* Wet, float* W1t, float* W2t, float* biasp,
                    float* h, float* ef, float* z, float* t,
                    float* outPart)
{
    // node proj: h = relu(x @ Wn + bn), dual-write z = h (layer 0 input)
    gemm_tc<<<NN / 128, 256, SMEM_BYTES>>>(x, Wnt, biasp, h, z,
                                           NODE_IN, NODE_IN, 64, 2, 1);
    // edge proj: ef = e @ We + be
    gemm_tc<<<NE / 128, 256, SMEM_BYTES>>>(e, Wet, biasp + NP, ef, nullptr,
                                           EDGE_IN, EDGE_IN, 32, 1, 0);

    for (int l = 0; l < 3; l++) {
        message_kernel<<<(NE * 38 + 255) / 256, 256>>>(h, ef, src, dst, z);
        gemm_tc<<<NN / 128, 256, SMEM_BYTES>>>(
            z, W1t + (size_t)l * NP * 320, biasp + (size_t)(2 + l) * NP,
            t, nullptr, NP, NP, 320, 10, 1);
        gemm_tc<<<NN / 128, 256, SMEM_BYTES>>>(
            t, W2t + (size_t)l * NP * 320, biasp + (size_t)(5 + l) * NP,
            h, (l < 2) ? z : nullptr, NP, NP, 320, 10, (l < 2) ? 1 : 0);
    }
    pool_kernel<<<(NN * 75 + 255) / 256, 256>>>(h, seg, outPart);
}

extern "C" void kernel_launch(void* const* d_in, const int* in_sizes, int n_in,
                              void* d_out, int out_size)
{
    const float* r_x = (const float*)d_in[0];
    const float* r_e = (const float*)d_in[1];
    const float* p_x = (const float*)d_in[2];
    const float* p_e = (const float*)d_in[3];
    const float* Wn  = (const float*)d_in[4];
    const float* bn  = (const float*)d_in[5];
    const float* We  = (const float*)d_in[6];
    const float* be  = (const float*)d_in[7];
    const float* W1  = (const float*)d_in[8];
    const float* b1  = (const float*)d_in[9];
    const float* W2  = (const float*)d_in[10];
    const float* b2  = (const float*)d_in[11];
    const int* r_src = (const int*)d_in[12];
    const int* r_dst = (const int*)d_in[13];
    const int* r_seg = (const int*)d_in[14];
    const int* p_src = (const int*)d_in[15];
    const int* p_dst = (const int*)d_in[16];
    const int* p_seg = (const int*)d_in[17];

    float* out   = (float*)d_out;
    float* r_sum = out + (size_t)BB * HH;
    float* p_sum = out + (size_t)2 * BB * HH;

    float *h, *ef, *z, *t, *Wnt, *Wet, *W1t, *W2t, *biasp;
    cudaGetSymbolAddress((void**)&h,    g_h);
    cudaGetSymbolAddress((void**)&ef,   g_ef);
    cudaGetSymbolAddress((void**)&z,    g_z);
    cudaGetSymbolAddress((void**)&t,    g_t);
    cudaGetSymbolAddress((void**)&Wnt,  g_Wnt);
    cudaGetSymbolAddress((void**)&Wet,  g_Wet);
    cudaGetSymbolAddress((void**)&W1t,  g_W1t);
    cudaGetSymbolAddress((void**)&W2t,  g_W2t);
    cudaGetSymbolAddress((void**)&biasp, g_biasp);

    static int s_attr_done = 0;
    if (!s_attr_done) {
        cudaFuncSetAttribute(gemm_tc, cudaFuncAttributeMaxDynamicSharedMemorySize,
                             SMEM_BYTES);
        s_attr_done = 1;
    }

    // prepack weights (transpose, pad) and biases
    pack_wt_kernel<<<(NP * 64 + 255) / 256, 256>>>(Wn, Wnt, NODE_IN, 64);
    pack_wt_kernel<<<(NP * 32 + 255) / 256, 256>>>(We, Wet, EDGE_IN, 32);
    for (int l = 0; l < 3; l++) {
        pack_wt_kernel<<<(NP * 320 + 255) / 256, 256>>>(
            W1 + (size_t)l * HH * HH, W1t + (size_t)l * NP * 320, HH, 320);
        pack_wt_kernel<<<(NP * 320 + 255) / 256, 256>>>(
            W2 + (size_t)l * HH * HH, W2t + (size_t)l * NP * 320, HH, 320);
    }
    pad_bias_kernel<<<1, NP>>>(bn, biasp);
    pad_bias_kernel<<<1, NP>>>(be, biasp + NP);
    for (int l = 0; l < 3; l++) {
        pad_bias_kernel<<<1, NP>>>(b1 + (size_t)l * HH, biasp + (size_t)(2 + l) * NP);
        pad_bias_kernel<<<1, NP>>>(b2 + (size_t)l * HH, biasp + (size_t)(5 + l) * NP);
    }

    // zero accumulation targets (r_sum, p_sum contiguous)
    zero_kernel<<<(2 * BB * HH + 255) / 256, 256>>>(r_sum, 2 * BB * HH);

    for (int g = 0; g < 2; g++) {
        run_gin(r_x + (size_t)g * NN * NODE_IN,
                r_e + (size_t)g * NE * EDGE_IN,
                r_src + (size_t)g * NE, r_dst + (size_t)g * NE,
                r_seg + (size_t)g * NN,
                Wnt, Wet, W1t, W2t, biasp,
                h, ef, z, t, r_sum);
    }
    run_gin(p_x, p_e, p_src, p_dst, p_seg,
            Wnt, Wet, W1t, W2t, biasp,
            h, ef, z, t, p_sum);

    diff_kernel<<<(BB * HH + 255) / 256, 256>>>(out);
}

// round 5
// speedup vs baseline: 1.9511x; 1.3946x over previous
#include <cuda_runtime.h>
#include <cuda_bf16.h>
#include <cstdint>

#define NN 122880      // nodes per graph
#define NE 245760      // edges per graph
#define HH 300         // hidden (logical)
#define NP 304         // hidden (padded row stride)
#define BB 4096        // reactions
#define NODE_IN 64
#define EDGE_IN 16

// smem geometry (bf16 tiles, 80-byte padded rows for conflict-free ldmatrix)
#define ROWB 80
#define A_HI_OFF 0
#define A_LO_OFF (128 * ROWB)                  // 10240
#define B_HI_OFF (2 * 128 * ROWB)              // 20480
#define B_LO_OFF (B_HI_OFF + 304 * ROWB)       // 44800
#define BUFSTRIDE (B_LO_OFF + 304 * ROWB)      // 69120
#define SMEM_BYTES (2 * BUFSTRIDE)             // 138240

// ---- scratch (device globals; no allocations allowed) ----
__device__ float g_h [(size_t)NN * NP];
__device__ float g_ef[(size_t)NE * NP];
__device__ float g_z [(size_t)NN * NP];
__device__ float g_t [(size_t)NN * NP];
__device__ __nv_bfloat16 g_Wnhi[(size_t)NP * 64];
__device__ __nv_bfloat16 g_Wnlo[(size_t)NP * 64];
__device__ __nv_bfloat16 g_Wehi[(size_t)NP * 32];
__device__ __nv_bfloat16 g_Welo[(size_t)NP * 32];
__device__ __nv_bfloat16 g_W1hi[(size_t)3 * NP * 320];
__device__ __nv_bfloat16 g_W1lo[(size_t)3 * NP * 320];
__device__ __nv_bfloat16 g_W2hi[(size_t)3 * NP * 320];
__device__ __nv_bfloat16 g_W2lo[(size_t)3 * NP * 320];
__device__ float g_biasp[(size_t)8 * NP];

// ============================ PTX helpers ============================
__device__ __forceinline__ uint32_t smem_u32(const void* p) {
    uint32_t a;
    asm("{ .reg .u64 t; cvta.to.shared.u64 t, %1; cvt.u32.u64 %0, t; }"
        : "=r"(a) : "l"(p));
    return a;
}
__device__ __forceinline__ void cp16(uint32_t dst, const void* src) {
    asm volatile("cp.async.cg.shared.global [%0], [%1], 16;"
                 :: "r"(dst), "l"(src) : "memory");
}
#define CP_COMMIT() asm volatile("cp.async.commit_group;" ::: "memory")

#define LDSM4(r, addr) \
    asm volatile("ldmatrix.sync.aligned.m8n8.x4.shared.b16 {%0,%1,%2,%3}, [%4];" \
        : "=r"((r)[0]), "=r"((r)[1]), "=r"((r)[2]), "=r"((r)[3]) : "r"(addr))
#define LDSM2(r, addr) \
    asm volatile("ldmatrix.sync.aligned.m8n8.x2.shared.b16 {%0,%1}, [%2];" \
        : "=r"((r)[0]), "=r"((r)[1]) : "r"(addr))

#define MMAB(d, a, b0, b1) \
    asm volatile("mma.sync.aligned.m16n8k16.row.col.f32.bf16.bf16.f32 " \
        "{%0,%1,%2,%3}, {%4,%5,%6,%7}, {%8,%9}, {%0,%1,%2,%3};" \
        : "+f"((d)[0]), "+f"((d)[1]), "+f"((d)[2]), "+f"((d)[3]) \
        : "r"((a)[0]), "r"((a)[1]), "r"((a)[2]), "r"((a)[3]), \
          "r"(b0), "r"(b1))

// split x,y into packed bf16x2 (hi, lo)
__device__ __forceinline__ void split_pack(float x, float y, uint32_t& hi, uint32_t& lo) {
    __nv_bfloat16 hx = __float2bfloat16_rn(x);
    __nv_bfloat16 hy = __float2bfloat16_rn(y);
    __nv_bfloat16 lx = __float2bfloat16_rn(x - __bfloat162float(hx));
    __nv_bfloat16 ly = __float2bfloat16_rn(y - __bfloat162float(hy));
    hi = (uint32_t)__bfloat16_as_ushort(hx) | ((uint32_t)__bfloat16_as_ushort(hy) << 16);
    lo = (uint32_t)__bfloat16_as_ushort(lx) | ((uint32_t)__bfloat16_as_ushort(ly) << 16);
}

// ============================ bf16-split tensor GEMM ============================
// C[M, NP] = (relu?)(A[M, Kact] @ W[Kact, 300->NP]); weights pre-split bf16 [n][Kp]
// grid.x = M/128, block = 256 (8 warps: 4 m-quarters x 2 n-halves)
__global__ __launch_bounds__(256, 1) void gemm_tc(
    const float* __restrict__ A,
    const __nv_bfloat16* __restrict__ Whi, const __nv_bfloat16* __restrict__ Wlo,
    const float* __restrict__ biasp, float* __restrict__ C,
    float* __restrict__ C2, int lda, int Kact, int kchunks, int doRelu)
{
    extern __shared__ char smem[];
    const uint32_t sb = smem_u32(smem);
    const int tid  = threadIdx.x;
    const int wid  = tid >> 5;
    const int lane = tid & 31;
    const int wm   = wid & 3;          // m quarter (32 rows)
    const int wn   = wid >> 2;         // n half (152 cols)
    const size_t rowBase = (size_t)blockIdx.x * 128;
    const int Kp = kchunks * 32;

    // ldmatrix per-lane offsets
    const int lr = lane & 7;
    const int g  = lane >> 3;
    // A x4: sub order (r0-7,k0-15bytes0-15? no: k dim bytes) -> see mapping
    const uint32_t aoff = ((uint32_t)(wm * 32 + lr + (g & 1) * 8)) * ROWB + ((g >> 1) << 4);
    // B x4 (2 n-tiles): subs: (n0-7,kb0),(n0-7,kb16),(n8-15,kb0),(n8-15,kb16)
    const uint32_t boff = ((uint32_t)(wn * 152 + lr + (g >> 1) * 8)) * ROWB + ((g & 1) << 4);
    // B x2 (last n-tile): lanes 0-15 used
    const uint32_t boff2 = ((uint32_t)(wn * 152 + 144 + lr)) * ROWB + ((g & 1) << 4);

    float acc[2][19][4];
#pragma unroll
    for (int i = 0; i < 2; i++)
#pragma unroll
        for (int j = 0; j < 19; j++)
#pragma unroll
            for (int q = 0; q < 4; q++) acc[i][j][q] = 0.f;

    float4 pre[4];
    auto ldg_regs = [&](int cidx) {
        const int k0 = cidx * 32;
#pragma unroll
        for (int i = 0; i < 4; ++i) {
            const int flat = tid + (i << 8);
            const int r = flat >> 3;
            const int j = flat & 7;
            const int k = k0 + (j << 2);
            pre[i] = (k < Kact) ? *(const float4*)(A + (rowBase + r) * lda + k)
                                : make_float4(0.f, 0.f, 0.f, 0.f);
        }
    };
    auto sts_regs = [&](int cidx) {
        char* base = smem + (cidx & 1) * BUFSTRIDE;
#pragma unroll
        for (int i = 0; i < 4; ++i) {
            const int flat = tid + (i << 8);
            const int r = flat >> 3;
            const int j = flat & 7;
            uint2 hi, lo;
            split_pack(pre[i].x, pre[i].y, hi.x, lo.x);
            split_pack(pre[i].z, pre[i].w, hi.y, lo.y);
            const uint32_t o = (uint32_t)r * ROWB + j * 8;
            *(uint2*)(base + A_HI_OFF + o) = hi;
            *(uint2*)(base + A_LO_OFF + o) = lo;
        }
    };
    auto cp_B = [&](int cidx) {
        const uint32_t base = sb + (cidx & 1) * BUFSTRIDE;
        const int k0 = cidx * 32;
#pragma unroll
        for (int i = 0; i < 10; ++i) {
            const int flat = tid + (i << 8);
            if (flat < 2432) {
                const int j = flat & 3;                 // 16B chunk within row
                const int idx = flat >> 2;              // 0..607
                const int isLo = idx >= 304;
                const int n = isLo ? idx - 304 : idx;
                const __nv_bfloat16* src = (isLo ? Wlo : Whi) + (size_t)n * Kp + k0 + j * 8;
                const uint32_t dst = base + (isLo ? B_LO_OFF : B_HI_OFF)
                                   + (uint32_t)n * ROWB + j * 16;
                cp16(dst, src);
            }
        }
        CP_COMMIT();
    };

    // prologue
    ldg_regs(0);
    sts_regs(0);
    cp_B(0);
    if (kchunks > 1) { cp_B(1); ldg_regs(1); }

    for (int c = 0; c < kchunks; ++c) {
        if (c + 1 < kchunks) asm volatile("cp.async.wait_group 1;" ::: "memory");
        else                 asm volatile("cp.async.wait_group 0;" ::: "memory");
        __syncthreads();

        if (c + 1 < kchunks) sts_regs(c + 1);
        if (c + 2 < kchunks) ldg_regs(c + 2);

        const uint32_t base = sb + (c & 1) * BUFSTRIDE;
#pragma unroll
        for (int ks = 0; ks < 2; ++ks) {
            const uint32_t kb = ks << 5;   // 16 bf16 = 32 bytes
            uint32_t ah[2][4], al[2][4];
#pragma unroll
            for (int mt = 0; mt < 2; ++mt) {
                const uint32_t ao = aoff + mt * (16 * ROWB) + kb;
                LDSM4(ah[mt], base + A_HI_OFF + ao);
                LDSM4(al[mt], base + A_LO_OFF + ao);
            }
#pragma unroll
            for (int ntp = 0; ntp < 9; ++ntp) {
                uint32_t bh[4], bl[4];
                const uint32_t bo = boff + (uint32_t)ntp * (16 * ROWB) + kb;
                LDSM4(bh, base + B_HI_OFF + bo);
                LDSM4(bl, base + B_LO_OFF + bo);
#pragma unroll
                for (int mt = 0; mt < 2; ++mt) {
                    MMAB(acc[mt][2 * ntp], al[mt], bh[0], bh[1]);
                    MMAB(acc[mt][2 * ntp], ah[mt], bl[0], bl[1]);
                    MMAB(acc[mt][2 * ntp], ah[mt], bh[0], bh[1]);
                    MMAB(acc[mt][2 * ntp + 1], al[mt], bh[2], bh[3]);
                    MMAB(acc[mt][2 * ntp + 1], ah[mt], bl[2], bl[3]);
                    MMAB(acc[mt][2 * ntp + 1], ah[mt], bh[2], bh[3]);
                }
            }
            uint32_t b2h[2], b2l[2];
            LDSM2(b2h, base + B_HI_OFF + boff2 + kb);
            LDSM2(b2l, base + B_LO_OFF + boff2 + kb);
#pragma unroll
            for (int mt = 0; mt < 2; ++mt) {
                MMAB(acc[mt][18], al[mt], b2h[0], b2h[1]);
                MMAB(acc[mt][18], ah[mt], b2l[0], b2l[1]);
                MMAB(acc[mt][18], ah[mt], b2h[0], b2h[1]);
            }
        }
        __syncthreads();
        if (c + 2 < kchunks) cp_B(c + 2);
    }

    // ---------- epilogue: bias + relu, direct float2 stores ----------
    const int colq = (lane & 3) * 2;
    const int rquad = lane >> 2;
#pragma unroll
    for (int mt = 0; mt < 2; ++mt) {
        const size_t row0 = rowBase + wm * 32 + mt * 16 + rquad;
#pragma unroll
        for (int nt = 0; nt < 19; ++nt) {
            const int col = wn * 152 + nt * 8 + colq;
            const float2 bv = *(const float2*)(biasp + col);
            float2 v01, v23;
            v01.x = acc[mt][nt][0] + bv.x;
            v01.y = acc[mt][nt][1] + bv.y;
            v23.x = acc[mt][nt][2] + bv.x;
            v23.y = acc[mt][nt][3] + bv.y;
            if (doRelu) {
                v01.x = fmaxf(v01.x, 0.f); v01.y = fmaxf(v01.y, 0.f);
                v23.x = fmaxf(v23.x, 0.f); v23.y = fmaxf(v23.y, 0.f);
            }
            const size_t o0 = row0 * NP + col;
            const size_t o1 = (row0 + 8) * NP + col;
            *(float2*)(C + o0) = v01;
            *(float2*)(C + o1) = v23;
            if (C2) {
                *(float2*)(C2 + o0) = v01;
                *(float2*)(C2 + o1) = v23;
            }
        }
    }
}

// ============ prepack: transpose + pad + bf16-split weights ============
__global__ __launch_bounds__(256) void pack_wt_kernel(
    const float* __restrict__ W, __nv_bfloat16* __restrict__ Whi,
    __nv_bfloat16* __restrict__ Wlo, int Kin, int Kp)
{
    const int idx = blockIdx.x * 256 + threadIdx.x;
    if (idx >= NP * Kp) return;
    const int n = idx / Kp;
    const int k = idx - n * Kp;
    float v = 0.f;
    if (k < Kin && n < HH) v = W[(size_t)k * HH + n];
    __nv_bfloat16 h = __float2bfloat16_rn(v);
    Whi[idx] = h;
    Wlo[idx] = __float2bfloat16_rn(v - __bfloat162float(h));
}
__global__ void pad_bias_kernel(const float* __restrict__ in, float* __restrict__ out)
{
    const int n = threadIdx.x;
    if (n < NP) out[n] = (n < HH) ? in[n] : 0.f;
}

// ============ message: z[dst] += relu(h[src] + ef), thread = edge x 8 cols ============
__global__ __launch_bounds__(256) void message_kernel(
    const float* __restrict__ h, const float* __restrict__ ef,
    const int* __restrict__ src, const int* __restrict__ dst,
    float* __restrict__ z)
{
    const int idx = blockIdx.x * blockDim.x + threadIdx.x;
    if (idx >= NE * 38) return;
    const int e = idx / 38;
    const int q = (idx - e * 38) << 3;
    const int s = __ldg(src + e);
    const int d = __ldg(dst + e);
    const float4* hp = (const float4*)(h + (size_t)s * NP + q);
    const float4* ep = (const float4*)(ef + (size_t)e * NP + q);
    const float4 h0 = hp[0], h1 = hp[1];
    const float4 e0 = ep[0], e1 = ep[1];
    float* zp = z + (size_t)d * NP + q;
    float m;
    m = h0.x + e0.x; if (m > 0.f) atomicAdd(zp + 0, m);
    m = h0.y + e0.y; if (m > 0.f) atomicAdd(zp + 1, m);
    m = h0.z + e0.z; if (m > 0.f) atomicAdd(zp + 2, m);
    m = h0.w + e0.w; if (m > 0.f) atomicAdd(zp + 3, m);
    m = h1.x + e1.x; if (m > 0.f) atomicAdd(zp + 4, m);
    m = h1.y + e1.y; if (m > 0.f) atomicAdd(zp + 5, m);
    m = h1.z + e1.z; if (m > 0.f) atomicAdd(zp + 6, m);
    m = h1.w + e1.w; if (m > 0.f) atomicAdd(zp + 7, m);
}

// ============ pool: out[seg[n]] += h[n] (300 cols) ============
__global__ __launch_bounds__(256) void pool_kernel(
    const float* __restrict__ h, const int* __restrict__ seg,
    float* __restrict__ out)
{
    const int idx = blockIdx.x * blockDim.x + threadIdx.x;
    if (idx >= NN * 75) return;
    const int n = idx / 75;
    const int q = (idx - n * 75) << 2;
    const int s = __ldg(seg + n);
    const float4 v = *(const float4*)(h + (size_t)n * NP + q);
    float* op = out + (size_t)s * HH + q;
    atomicAdd(op + 0, v.x);
    atomicAdd(op + 1, v.y);
    atomicAdd(op + 2, v.z);
    atomicAdd(op + 3, v.w);
}

__global__ __launch_bounds__(256) void zero_kernel(float* __restrict__ p, int n)
{
    const int idx = blockIdx.x * blockDim.x + threadIdx.x;
    if (idx < n) p[idx] = 0.f;
}

__global__ __launch_bounds__(256) void diff_kernel(float* __restrict__ out)
{
    const int idx = blockIdx.x * blockDim.x + threadIdx.x;
    const int BH = BB * HH;
    if (idx < BH) out[idx] = out[BH + idx] - out[2 * BH + idx];
}

// ============================== host orchestration ==============================
static void run_gin(const float* x, const float* e,
                    const int* src, const int* dst, const int* seg,
                    __nv_bfloat16* Wnhi, __nv_bfloat16* Wnlo,
                    __nv_bfloat16* Wehi, __nv_bfloat16* Welo,
                    __nv_bfloat16* W1hi, __nv_bfloat16* W1lo,
                    __nv_bfloat16* W2hi, __nv_bfloat16* W2lo,
                    float* biasp,
                    float* h, float* ef, float* z, float* t,
                    float* outPart)
{
    // node proj: h = relu(x @ Wn + bn), dual-write z = h (layer 0 input)
    gemm_tc<<<NN / 128, 256, SMEM_BYTES>>>(x, Wnhi, Wnlo, biasp, h, z,
                                           NODE_IN, NODE_IN, 2, 1);
    // edge proj: ef = e @ We + be
    gemm_tc<<<NE / 128, 256, SMEM_BYTES>>>(e, Wehi, Welo, biasp + NP, ef, nullptr,
                                           EDGE_IN, EDGE_IN, 1, 0);

    for (int l = 0; l < 3; l++) {
        message_kernel<<<(NE * 38 + 255) / 256, 256>>>(h, ef, src, dst, z);
        gemm_tc<<<NN / 128, 256, SMEM_BYTES>>>(
            z, W1hi + (size_t)l * NP * 320, W1lo + (size_t)l * NP * 320,
            biasp + (size_t)(2 + l) * NP, t, nullptr, NP, NP, 10, 1);
        gemm_tc<<<NN / 128, 256, SMEM_BYTES>>>(
            t, W2hi + (size_t)l * NP * 320, W2lo + (size_t)l * NP * 320,
            biasp + (size_t)(5 + l) * NP, h, (l < 2) ? z : nullptr,
            NP, NP, 10, (l < 2) ? 1 : 0);
    }
    pool_kernel<<<(NN * 75 + 255) / 256, 256>>>(h, seg, outPart);
}

extern "C" void kernel_launch(void* const* d_in, const int* in_sizes, int n_in,
                              void* d_out, int out_size)
{
    const float* r_x = (const float*)d_in[0];
    const float* r_e = (const float*)d_in[1];
    const float* p_x = (const float*)d_in[2];
    const float* p_e = (const float*)d_in[3];
    const float* Wn  = (const float*)d_in[4];
    const float* bn  = (const float*)d_in[5];
    const float* We  = (const float*)d_in[6];
    const float* be  = (const float*)d_in[7];
    const float* W1  = (const float*)d_in[8];
    const float* b1  = (const float*)d_in[9];
    const float* W2  = (const float*)d_in[10];
    const float* b2  = (const float*)d_in[11];
    const int* r_src = (const int*)d_in[12];
    const int* r_dst = (const int*)d_in[13];
    const int* r_seg = (const int*)d_in[14];
    const int* p_src = (const int*)d_in[15];
    const int* p_dst = (const int*)d_in[16];
    const int* p_seg = (const int*)d_in[17];

    float* out   = (float*)d_out;
    float* r_sum = out + (size_t)BB * HH;
    float* p_sum = out + (size_t)2 * BB * HH;

    float *h, *ef, *z, *t, *biasp;
    __nv_bfloat16 *Wnhi, *Wnlo, *Wehi, *Welo, *W1hi, *W1lo, *W2hi, *W2lo;
    cudaGetSymbolAddress((void**)&h,    g_h);
    cudaGetSymbolAddress((void**)&ef,   g_ef);
    cudaGetSymbolAddress((void**)&z,    g_z);
    cudaGetSymbolAddress((void**)&t,    g_t);
    cudaGetSymbolAddress((void**)&Wnhi, g_Wnhi);
    cudaGetSymbolAddress((void**)&Wnlo, g_Wnlo);
    cudaGetSymbolAddress((void**)&Wehi, g_Wehi);
    cudaGetSymbolAddress((void**)&Welo, g_Welo);
    cudaGetSymbolAddress((void**)&W1hi, g_W1hi);
    cudaGetSymbolAddress((void**)&W1lo, g_W1lo);
    cudaGetSymbolAddress((void**)&W2hi, g_W2hi);
    cudaGetSymbolAddress((void**)&W2lo, g_W2lo);
    cudaGetSymbolAddress((void**)&biasp, g_biasp);

    cudaFuncSetAttribute(gemm_tc, cudaFuncAttributeMaxDynamicSharedMemorySize,
                         SMEM_BYTES);

    // prepack weights (transpose, pad, bf16 split) and biases
    pack_wt_kernel<<<(NP * 64 + 255) / 256, 256>>>(Wn, Wnhi, Wnlo, NODE_IN, 64);
    pack_wt_kernel<<<(NP * 32 + 255) / 256, 256>>>(We, Wehi, Welo, EDGE_IN, 32);
    for (int l = 0; l < 3; l++) {
        pack_wt_kernel<<<(NP * 320 + 255) / 256, 256>>>(
            W1 + (size_t)l * HH * HH, W1hi + (size_t)l * NP * 320,
            W1lo + (size_t)l * NP * 320, HH, 320);
        pack_wt_kernel<<<(NP * 320 + 255) / 256, 256>>>(
            W2 + (size_t)l * HH * HH, W2hi + (size_t)l * NP * 320,
            W2lo + (size_t)l * NP * 320, HH, 320);
    }
    pad_bias_kernel<<<1, NP>>>(bn, biasp);
    pad_bias_kernel<<<1, NP>>>(be, biasp + NP);
    for (int l = 0; l < 3; l++) {
        pad_bias_kernel<<<1, NP>>>(b1 + (size_t)l * HH, biasp + (size_t)(2 + l) * NP);
        pad_bias_kernel<<<1, NP>>>(b2 + (size_t)l * HH, biasp + (size_t)(5 + l) * NP);
    }

    // zero accumulation targets (r_sum, p_sum contiguous)
    zero_kernel<<<(2 * BB * HH + 255) / 256, 256>>>(r_sum, 2 * BB * HH);

    for (int g = 0; g < 2; g++) {
        run_gin(r_x + (size_t)g * NN * NODE_IN,
                r_e + (size_t)g * NE * EDGE_IN,
                r_src + (size_t)g * NE, r_dst + (size_t)g * NE,
                r_seg + (size_t)g * NN,
                Wnhi, Wnlo, Wehi, Welo, W1hi, W1lo, W2hi, W2lo, biasp,
                h, ef, z, t, r_sum);
    }
    run_gin(p_x, p_e, p_src, p_dst, p_seg,
            Wnhi, Wnlo, Wehi, Welo, W1hi, W1lo, W2hi, W2lo, biasp,
            h, ef, z, t, p_sum);

    diff_kernel<<<(BB * HH + 255) / 256, 256>>>(out);
}

// round 6
// speedup vs baseline: 2.1218x; 1.0874x over previous
#include <cuda_runtime.h>
#include <cuda_bf16.h>
#include <cstdint>

#define NN 122880      // nodes per graph
#define NE 245760      // edges per graph
#define HH 300         // hidden (logical)
#define NP 304         // hidden (padded row stride)
#define BB 4096        // reactions
#define NODE_IN 64
#define EDGE_IN 16

// smem geometry (bf16 tiles, 80-byte padded rows for conflict-free ldmatrix)
// CTA tile: 128 rows x 152 cols
#define ROWB 80
#define A_HI_OFF 0
#define A_LO_OFF (128 * ROWB)                  // 10240
#define B_HI_OFF (2 * 128 * ROWB)              // 20480
#define B_LO_OFF (B_HI_OFF + 152 * ROWB)       // 32640
#define BUFSTRIDE (B_LO_OFF + 152 * ROWB)      // 44800
#define SMEM_BYTES (2 * BUFSTRIDE)             // 89600

// ---- scratch (device globals; no allocations allowed) ----
__device__ float g_h [(size_t)NN * NP];
__device__ float g_ef[(size_t)NE * NP];
__device__ float g_z [(size_t)NN * NP];
__device__ float g_t [(size_t)NN * NP];
__device__ __nv_bfloat16 g_Wnhi[(size_t)NP * 64];
__device__ __nv_bfloat16 g_Wnlo[(size_t)NP * 64];
__device__ __nv_bfloat16 g_Wehi[(size_t)NP * 32];
__device__ __nv_bfloat16 g_Welo[(size_t)NP * 32];
__device__ __nv_bfloat16 g_W1hi[(size_t)3 * NP * 320];
__device__ __nv_bfloat16 g_W1lo[(size_t)3 * NP * 320];
__device__ __nv_bfloat16 g_W2hi[(size_t)3 * NP * 320];
__device__ __nv_bfloat16 g_W2lo[(size_t)3 * NP * 320];
__device__ float g_biasp[(size_t)8 * NP];

// ============================ PTX helpers ============================
__device__ __forceinline__ uint32_t smem_u32(const void* p) {
    uint32_t a;
    asm("{ .reg .u64 t; cvta.to.shared.u64 t, %1; cvt.u32.u64 %0, t; }"
        : "=r"(a) : "l"(p));
    return a;
}
__device__ __forceinline__ void cp16(uint32_t dst, const void* src) {
    asm volatile("cp.async.cg.shared.global [%0], [%1], 16;"
                 :: "r"(dst), "l"(src) : "memory");
}
#define CP_COMMIT() asm volatile("cp.async.commit_group;" ::: "memory")

#define LDSM4(r, addr) \
    asm volatile("ldmatrix.sync.aligned.m8n8.x4.shared.b16 {%0,%1,%2,%3}, [%4];" \
        : "=r"((r)[0]), "=r"((r)[1]), "=r"((r)[2]), "=r"((r)[3]) : "r"(addr))
#define LDSM2(r, addr) \
    asm volatile("ldmatrix.sync.aligned.m8n8.x2.shared.b16 {%0,%1}, [%2];" \
        : "=r"((r)[0]), "=r"((r)[1]) : "r"(addr))

#define MMAB(d, a, b0, b1) \
    asm volatile("mma.sync.aligned.m16n8k16.row.col.f32.bf16.bf16.f32 " \
        "{%0,%1,%2,%3}, {%4,%5,%6,%7}, {%8,%9}, {%0,%1,%2,%3};" \
        : "+f"((d)[0]), "+f"((d)[1]), "+f"((d)[2]), "+f"((d)[3]) \
        : "r"((a)[0]), "r"((a)[1]), "r"((a)[2]), "r"((a)[3]), \
          "r"(b0), "r"(b1))

// split x,y into packed bf16x2 (hi, lo)
__device__ __forceinline__ void split_pack(float x, float y, uint32_t& hi, uint32_t& lo) {
    __nv_bfloat16 hx = __float2bfloat16_rn(x);
    __nv_bfloat16 hy = __float2bfloat16_rn(y);
    __nv_bfloat16 lx = __float2bfloat16_rn(x - __bfloat162float(hx));
    __nv_bfloat16 ly = __float2bfloat16_rn(y - __bfloat162float(hy));
    hi = (uint32_t)__bfloat16_as_ushort(hx) | ((uint32_t)__bfloat16_as_ushort(hy) << 16);
    lo = (uint32_t)__bfloat16_as_ushort(lx) | ((uint32_t)__bfloat16_as_ushort(ly) << 16);
}

// ============================ bf16-split tensor GEMM ============================
// C tile = 128 rows x 152 cols per CTA; grid = (M/128, 2 n-halves); 4 warps.
__global__ __launch_bounds__(128, 2) void gemm_tc(
    const float* __restrict__ A,
    const __nv_bfloat16* __restrict__ Whi, const __nv_bfloat16* __restrict__ Wlo,
    const float* __restrict__ biasp, float* __restrict__ C,
    float* __restrict__ C2, int lda, int Kact, int kchunks, int doRelu)
{
    extern __shared__ char smem[];
    const uint32_t sb = smem_u32(smem);
    const int tid  = threadIdx.x;
    const int wid  = tid >> 5;         // m quarter (32 rows)
    const int lane = tid & 31;
    const size_t rowBase = (size_t)blockIdx.x * 128;
    const int nBase = blockIdx.y * 152;   // n-half origin (global col)
    const int Kp = kchunks * 32;

    // ldmatrix per-lane offsets
    const int lr = lane & 7;
    const int g  = lane >> 3;
    const uint32_t aoff = ((uint32_t)(wid * 32 + lr + (g & 1) * 8)) * ROWB + ((g >> 1) << 4);
    const uint32_t boff = ((uint32_t)(lr + (g >> 1) * 8)) * ROWB + ((g & 1) << 4);
    const uint32_t boff2 = ((uint32_t)(144 + lr)) * ROWB + ((g & 1) << 4);

    float acc[2][19][4];
#pragma unroll
    for (int i = 0; i < 2; i++)
#pragma unroll
        for (int j = 0; j < 19; j++)
#pragma unroll
            for (int q = 0; q < 4; q++) acc[i][j][q] = 0.f;

    float4 pre[8];
    auto ldg_regs = [&](int cidx) {
        const int k0 = cidx * 32;
#pragma unroll
        for (int i = 0; i < 8; ++i) {
            const int flat = tid + (i << 7);
            const int r = flat >> 3;
            const int j = flat & 7;
            const int k = k0 + (j << 2);
            pre[i] = (k < Kact) ? *(const float4*)(A + (rowBase + r) * lda + k)
                                : make_float4(0.f, 0.f, 0.f, 0.f);
        }
    };
    auto sts_regs = [&](int cidx) {
        char* base = smem + (cidx & 1) * BUFSTRIDE;
#pragma unroll
        for (int i = 0; i < 8; ++i) {
            const int flat = tid + (i << 7);
            const int r = flat >> 3;
            const int j = flat & 7;
            uint2 hi, lo;
            split_pack(pre[i].x, pre[i].y, hi.x, lo.x);
            split_pack(pre[i].z, pre[i].w, hi.y, lo.y);
            const uint32_t o = (uint32_t)r * ROWB + j * 8;
            *(uint2*)(base + A_HI_OFF + o) = hi;
            *(uint2*)(base + A_LO_OFF + o) = lo;
        }
    };
    auto cp_B = [&](int cidx) {
        const uint32_t base = sb + (cidx & 1) * BUFSTRIDE;
        const int k0 = cidx * 32;
#pragma unroll
        for (int i = 0; i < 10; ++i) {
            const int flat = tid + (i << 7);
            if (flat < 1216) {
                const int j = flat & 3;                 // 16B chunk within row
                const int idx = flat >> 2;              // 0..303
                const int isLo = idx >= 152;
                const int n = isLo ? idx - 152 : idx;
                const __nv_bfloat16* src =
                    (isLo ? Wlo : Whi) + (size_t)(nBase + n) * Kp + k0 + j * 8;
                const uint32_t dst = base + (isLo ? B_LO_OFF : B_HI_OFF)
                                   + (uint32_t)n * ROWB + j * 16;
                cp16(dst, src);
            }
        }
        CP_COMMIT();
    };

    // prologue
    ldg_regs(0);
    sts_regs(0);
    cp_B(0);
    if (kchunks > 1) { cp_B(1); ldg_regs(1); }

    for (int c = 0; c < kchunks; ++c) {
        if (c + 1 < kchunks) asm volatile("cp.async.wait_group 1;" ::: "memory");
        else                 asm volatile("cp.async.wait_group 0;" ::: "memory");
        __syncthreads();

        if (c + 1 < kchunks) sts_regs(c + 1);
        if (c + 2 < kchunks) ldg_regs(c + 2);

        const uint32_t base = sb + (c & 1) * BUFSTRIDE;
#pragma unroll
        for (int ks = 0; ks < 2; ++ks) {
            const uint32_t kb = ks << 5;   // 16 bf16 = 32 bytes
            uint32_t ah[2][4], al[2][4];
#pragma unroll
            for (int mt = 0; mt < 2; ++mt) {
                const uint32_t ao = aoff + mt * (16 * ROWB) + kb;
                LDSM4(ah[mt], base + A_HI_OFF + ao);
                LDSM4(al[mt], base + A_LO_OFF + ao);
            }
#pragma unroll
            for (int ntp = 0; ntp < 9; ++ntp) {
                uint32_t bh[4], bl[4];
                const uint32_t bo = boff + (uint32_t)ntp * (16 * ROWB) + kb;
                LDSM4(bh, base + B_HI_OFF + bo);
                LDSM4(bl, base + B_LO_OFF + bo);
                // term-major ordering: same-acc reuse distance = 4 MMAs
#pragma unroll
                for (int mt = 0; mt < 2; ++mt) {
                    MMAB(acc[mt][2 * ntp],     al[mt], bh[0], bh[1]);
                    MMAB(acc[mt][2 * ntp + 1], al[mt], bh[2], bh[3]);
                }
#pragma unroll
                for (int mt = 0; mt < 2; ++mt) {
                    MMAB(acc[mt][2 * ntp],     ah[mt], bl[0], bl[1]);
                    MMAB(acc[mt][2 * ntp + 1], ah[mt], bl[2], bl[3]);
                }
#pragma unroll
                for (int mt = 0; mt < 2; ++mt) {
                    MMAB(acc[mt][2 * ntp],     ah[mt], bh[0], bh[1]);
                    MMAB(acc[mt][2 * ntp + 1], ah[mt], bh[2], bh[3]);
                }
            }
            uint32_t b2h[2], b2l[2];
            LDSM2(b2h, base + B_HI_OFF + boff2 + kb);
            LDSM2(b2l, base + B_LO_OFF + boff2 + kb);
#pragma unroll
            for (int mt = 0; mt < 2; ++mt)
                MMAB(acc[mt][18], al[mt], b2h[0], b2h[1]);
#pragma unroll
            for (int mt = 0; mt < 2; ++mt)
                MMAB(acc[mt][18], ah[mt], b2l[0], b2l[1]);
#pragma unroll
            for (int mt = 0; mt < 2; ++mt)
                MMAB(acc[mt][18], ah[mt], b2h[0], b2h[1]);
        }
        __syncthreads();
        if (c + 2 < kchunks) cp_B(c + 2);
    }

    // ---------- epilogue: bias + relu, direct float2 stores ----------
    const int colq = (lane & 3) * 2;
    const int rquad = lane >> 2;
#pragma unroll
    for (int mt = 0; mt < 2; ++mt) {
        const size_t row0 = rowBase + wid * 32 + mt * 16 + rquad;
#pragma unroll
        for (int nt = 0; nt < 19; ++nt) {
            const int col = nBase + nt * 8 + colq;
            const float2 bv = *(const float2*)(biasp + col);
            float2 v01, v23;
            v01.x = acc[mt][nt][0] + bv.x;
            v01.y = acc[mt][nt][1] + bv.y;
            v23.x = acc[mt][nt][2] + bv.x;
            v23.y = acc[mt][nt][3] + bv.y;
            if (doRelu) {
                v01.x = fmaxf(v01.x, 0.f); v01.y = fmaxf(v01.y, 0.f);
                v23.x = fmaxf(v23.x, 0.f); v23.y = fmaxf(v23.y, 0.f);
            }
            const size_t o0 = row0 * NP + col;
            const size_t o1 = (row0 + 8) * NP + col;
            *(float2*)(C + o0) = v01;
            *(float2*)(C + o1) = v23;
            if (C2) {
                *(float2*)(C2 + o0) = v01;
                *(float2*)(C2 + o1) = v23;
            }
        }
    }
}

// ============ prepack: transpose + pad + bf16-split weights ============
__global__ __launch_bounds__(256) void pack_wt_kernel(
    const float* __restrict__ W, __nv_bfloat16* __restrict__ Whi,
    __nv_bfloat16* __restrict__ Wlo, int Kin, int Kp)
{
    const int idx = blockIdx.x * 256 + threadIdx.x;
    if (idx >= NP * Kp) return;
    const int n = idx / Kp;
    const int k = idx - n * Kp;
    float v = 0.f;
    if (k < Kin && n < HH) v = W[(size_t)k * HH + n];
    __nv_bfloat16 h = __float2bfloat16_rn(v);
    Whi[idx] = h;
    Wlo[idx] = __float2bfloat16_rn(v - __bfloat162float(h));
}
__global__ void pad_bias_kernel(const float* __restrict__ in, float* __restrict__ out)
{
    const int n = threadIdx.x;
    if (n < NP) out[n] = (n < HH) ? in[n] : 0.f;
}

// ============ message: z[dst] += relu(h[src] + ef), thread = edge x 8 cols ============
__global__ __launch_bounds__(256) void message_kernel(
    const float* __restrict__ h, const float* __restrict__ ef,
    const int* __restrict__ src, const int* __restrict__ dst,
    float* __restrict__ z)
{
    const int idx = blockIdx.x * blockDim.x + threadIdx.x;
    if (idx >= NE * 38) return;
    const int e = idx / 38;
    const int q = (idx - e * 38) << 3;
    const int s = __ldg(src + e);
    const int d = __ldg(dst + e);
    const float4* hp = (const float4*)(h + (size_t)s * NP + q);
    const float4* ep = (const float4*)(ef + (size_t)e * NP + q);
    const float4 h0 = hp[0], h1 = hp[1];
    const float4 e0 = ep[0], e1 = ep[1];
    float* zp = z + (size_t)d * NP + q;
    float m;
    m = h0.x + e0.x; if (m > 0.f) atomicAdd(zp + 0, m);
    m = h0.y + e0.y; if (m > 0.f) atomicAdd(zp + 1, m);
    m = h0.z + e0.z; if (m > 0.f) atomicAdd(zp + 2, m);
    m = h0.w + e0.w; if (m > 0.f) atomicAdd(zp + 3, m);
    m = h1.x + e1.x; if (m > 0.f) atomicAdd(zp + 4, m);
    m = h1.y + e1.y; if (m > 0.f) atomicAdd(zp + 5, m);
    m = h1.z + e1.z; if (m > 0.f) atomicAdd(zp + 6, m);
    m = h1.w + e1.w; if (m > 0.f) atomicAdd(zp + 7, m);
}

// ============ pool: out[seg[n]] += h[n] (300 cols) ============
__global__ __launch_bounds__(256) void pool_kernel(
    const float* __restrict__ h, const int* __restrict__ seg,
    float* __restrict__ out)
{
    const int idx = blockIdx.x * blockDim.x + threadIdx.x;
    if (idx >= NN * 75) return;
    const int n = idx / 75;
    const int q = (idx - n * 75) << 2;
    const int s = __ldg(seg + n);
    const float4 v = *(const float4*)(h + (size_t)n * NP + q);
    float* op = out + (size_t)s * HH + q;
    atomicAdd(op + 0, v.x);
    atomicAdd(op + 1, v.y);
    atomicAdd(op + 2, v.z);
    atomicAdd(op + 3, v.w);
}

__global__ __launch_bounds__(256) void zero_kernel(float* __restrict__ p, int n)
{
    const int idx = blockIdx.x * blockDim.x + threadIdx.x;
    if (idx < n) p[idx] = 0.f;
}

__global__ __launch_bounds__(256) void diff_kernel(float* __restrict__ out)
{
    const int idx = blockIdx.x * blockDim.x + threadIdx.x;
    const int BH = BB * HH;
    if (idx < BH) out[idx] = out[BH + idx] - out[2 * BH + idx];
}

// ============================== host orchestration ==============================
static void run_gin(const float* x, const float* e,
                    const int* src, const int* dst, const int* seg,
                    __nv_bfloat16* Wnhi, __nv_bfloat16* Wnlo,
                    __nv_bfloat16* Wehi, __nv_bfloat16* Welo,
                    __nv_bfloat16* W1hi, __nv_bfloat16* W1lo,
                    __nv_bfloat16* W2hi, __nv_bfloat16* W2lo,
                    float* biasp,
                    float* h, float* ef, float* z, float* t,
                    float* outPart)
{
    const dim3 gN(NN / 128, 2);
    const dim3 gE(NE / 128, 2);

    // node proj: h = relu(x @ Wn + bn), dual-write z = h (layer 0 input)
    gemm_tc<<<gN, 128, SMEM_BYTES>>>(x, Wnhi, Wnlo, biasp, h, z,
                                     NODE_IN, NODE_IN, 2, 1);
    // edge proj: ef = e @ We + be
    gemm_tc<<<gE, 128, SMEM_BYTES>>>(e, Wehi, Welo, biasp + NP, ef, nullptr,
                                     EDGE_IN, EDGE_IN, 1, 0);

    for (int l = 0; l < 3; l++) {
        message_kernel<<<(NE * 38 + 255) / 256, 256>>>(h, ef, src, dst, z);
        gemm_tc<<<gN, 128, SMEM_BYTES>>>(
            z, W1hi + (size_t)l * NP * 320, W1lo + (size_t)l * NP * 320,
            biasp + (size_t)(2 + l) * NP, t, nullptr, NP, NP, 10, 1);
        gemm_tc<<<gN, 128, SMEM_BYTES>>>(
            t, W2hi + (size_t)l * NP * 320, W2lo + (size_t)l * NP * 320,
            biasp + (size_t)(5 + l) * NP, h, (l < 2) ? z : nullptr,
            NP, NP, 10, (l < 2) ? 1 : 0);
    }
    pool_kernel<<<(NN * 75 + 255) / 256, 256>>>(h, seg, outPart);
}

extern "C" void kernel_launch(void* const* d_in, const int* in_sizes, int n_in,
                              void* d_out, int out_size)
{
    const float* r_x = (const float*)d_in[0];
    const float* r_e = (const float*)d_in[1];
    const float* p_x = (const float*)d_in[2];
    const float* p_e = (const float*)d_in[3];
    const float* Wn  = (const float*)d_in[4];
    const float* bn  = (const float*)d_in[5];
    const float* We  = (const float*)d_in[6];
    const float* be  = (const float*)d_in[7];
    const float* W1  = (const float*)d_in[8];
    const float* b1  = (const float*)d_in[9];
    const float* W2  = (const float*)d_in[10];
    const float* b2  = (const float*)d_in[11];
    const int* r_src = (const int*)d_in[12];
    const int* r_dst = (const int*)d_in[13];
    const int* r_seg = (const int*)d_in[14];
    const int* p_src = (const int*)d_in[15];
    const int* p_dst = (const int*)d_in[16];
    const int* p_seg = (const int*)d_in[17];

    float* out   = (float*)d_out;
    float* r_sum = out + (size_t)BB * HH;
    float* p_sum = out + (size_t)2 * BB * HH;

    float *h, *ef, *z, *t, *biasp;
    __nv_bfloat16 *Wnhi, *Wnlo, *Wehi, *Welo, *W1hi, *W1lo, *W2hi, *W2lo;
    cudaGetSymbolAddress((void**)&h,    g_h);
    cudaGetSymbolAddress((void**)&ef,   g_ef);
    cudaGetSymbolAddress((void**)&z,    g_z);
    cudaGetSymbolAddress((void**)&t,    g_t);
    cudaGetSymbolAddress((void**)&Wnhi, g_Wnhi);
    cudaGetSymbolAddress((void**)&Wnlo, g_Wnlo);
    cudaGetSymbolAddress((void**)&Wehi, g_Wehi);
    cudaGetSymbolAddress((void**)&Welo, g_Welo);
    cudaGetSymbolAddress((void**)&W1hi, g_W1hi);
    cudaGetSymbolAddress((void**)&W1lo, g_W1lo);
    cudaGetSymbolAddress((void**)&W2hi, g_W2hi);
    cudaGetSymbolAddress((void**)&W2lo, g_W2lo);
    cudaGetSymbolAddress((void**)&biasp, g_biasp);

    cudaFuncSetAttribute(gemm_tc, cudaFuncAttributeMaxDynamicSharedMemorySize,
                         SMEM_BYTES);

    // prepack weights (transpose, pad, bf16 split) and biases
    pack_wt_kernel<<<(NP * 64 + 255) / 256, 256>>>(Wn, Wnhi, Wnlo, NODE_IN, 64);
    pack_wt_kernel<<<(NP * 32 + 255) / 256, 256>>>(We, Wehi, Welo, EDGE_IN, 32);
    for (int l = 0; l < 3; l++) {
        pack_wt_kernel<<<(NP * 320 + 255) / 256, 256>>>(
            W1 + (size_t)l * HH * HH, W1hi + (size_t)l * NP * 320,
            W1lo + (size_t)l * NP * 320, HH, 320);
        pack_wt_kernel<<<(NP * 320 + 255) / 256, 256>>>(
            W2 + (size_t)l * HH * HH, W2hi + (size_t)l * NP * 320,
            W2lo + (size_t)l * NP * 320, HH, 320);
    }
    pad_bias_kernel<<<1, NP>>>(bn, biasp);
    pad_bias_kernel<<<1, NP>>>(be, biasp + NP);
    for (int l = 0; l < 3; l++) {
        pad_bias_kernel<<<1, NP>>>(b1 + (size_t)l * HH, biasp + (size_t)(2 + l) * NP);
        pad_bias_kernel<<<1, NP>>>(b2 + (size_t)l * HH, biasp + (size_t)(5 + l) * NP);
    }

    // zero accumulation targets (r_sum, p_sum contiguous)
    zero_kernel<<<(2 * BB * HH + 255) / 256, 256>>>(r_sum, 2 * BB * HH);

    for (int g = 0; g < 2; g++) {
        run_gin(r_x + (size_t)g * NN * NODE_IN,
                r_e + (size_t)g * NE * EDGE_IN,
                r_src + (size_t)g * NE, r_dst + (size_t)g * NE,
                r_seg + (size_t)g * NN,
                Wnhi, Wnlo, Wehi, Welo, W1hi, W1lo, W2hi, W2lo, biasp,
                h, ef, z, t, r_sum);
    }
    run_gin(p_x, p_e, p_src, p_dst, p_seg,
            Wnhi, Wnlo, Wehi, Welo, W1hi, W1lo, W2hi, W2lo, biasp,
            h, ef, z, t, p_sum);

    diff_kernel<<<(BB * HH + 255) / 256, 256>>>(out);
}

// round 7
// speedup vs baseline: 2.2154x; 1.0441x over previous
#include <cuda_runtime.h>
#include <cuda_bf16.h>
#include <cstdint>

#define NN 122880      // nodes per graph
#define NE 245760      // edges per graph
#define HH 300         // hidden (logical)
#define NP 304         // hidden (padded row stride)
#define BB 4096        // reactions
#define NODE_IN 64
#define EDGE_IN 16

// smem geometry (bf16 tiles, 80-byte padded rows for conflict-free ldmatrix)
// CTA tile: 128 rows x 152 cols
#define ROWB 80
#define A_HI_OFF 0
#define A_LO_OFF (128 * ROWB)                  // 10240
#define B_HI_OFF (2 * 128 * ROWB)              // 20480
#define B_LO_OFF (B_HI_OFF + 152 * ROWB)       // 32640
#define BUFSTRIDE (B_LO_OFF + 152 * ROWB)      // 44800
#define SMEM_BYTES (2 * BUFSTRIDE)             // 89600

// ---- scratch (device globals; no allocations allowed) ----
__device__ float g_h [(size_t)NN * NP];
__device__ float g_ef[(size_t)NE * NP];
__device__ float g_z [(size_t)NN * NP];
__device__ float g_t [(size_t)NN * NP];
__device__ __nv_bfloat16 g_Wnhi[(size_t)NP * 64];
__device__ __nv_bfloat16 g_Wnlo[(size_t)NP * 64];
__device__ __nv_bfloat16 g_Wehi[(size_t)NP * 32];
__device__ __nv_bfloat16 g_Welo[(size_t)NP * 32];
__device__ __nv_bfloat16 g_W1hi[(size_t)3 * NP * 320];
__device__ __nv_bfloat16 g_W1lo[(size_t)3 * NP * 320];
__device__ __nv_bfloat16 g_W2hi[(size_t)3 * NP * 320];
__device__ __nv_bfloat16 g_W2lo[(size_t)3 * NP * 320];
__device__ float g_biasp[(size_t)8 * NP];

// ============================ PTX helpers ============================
__device__ __forceinline__ uint32_t smem_u32(const void* p) {
    uint32_t a;
    asm("{ .reg .u64 t; cvta.to.shared.u64 t, %1; cvt.u32.u64 %0, t; }"
        : "=r"(a) : "l"(p));
    return a;
}
__device__ __forceinline__ void cp16(uint32_t dst, const void* src) {
    asm volatile("cp.async.cg.shared.global [%0], [%1], 16;"
                 :: "r"(dst), "l"(src) : "memory");
}
#define CP_COMMIT() asm volatile("cp.async.commit_group;" ::: "memory")

#define LDSM4(r, addr) \
    asm volatile("ldmatrix.sync.aligned.m8n8.x4.shared.b16 {%0,%1,%2,%3}, [%4];" \
        : "=r"((r)[0]), "=r"((r)[1]), "=r"((r)[2]), "=r"((r)[3]) : "r"(addr))
#define LDSM2(r, addr) \
    asm volatile("ldmatrix.sync.aligned.m8n8.x2.shared.b16 {%0,%1}, [%2];" \
        : "=r"((r)[0]), "=r"((r)[1]) : "r"(addr))

#define MMAB(d, a, b0, b1) \
    asm volatile("mma.sync.aligned.m16n8k16.row.col.f32.bf16.bf16.f32 " \
        "{%0,%1,%2,%3}, {%4,%5,%6,%7}, {%8,%9}, {%0,%1,%2,%3};" \
        : "+f"((d)[0]), "+f"((d)[1]), "+f"((d)[2]), "+f"((d)[3]) \
        : "r"((a)[0]), "r"((a)[1]), "r"((a)[2]), "r"((a)[3]), \
          "r"(b0), "r"(b1))

// split x,y into packed bf16x2 (hi, lo)
__device__ __forceinline__ void split_pack(float x, float y, uint32_t& hi, uint32_t& lo) {
    __nv_bfloat16 hx = __float2bfloat16_rn(x);
    __nv_bfloat16 hy = __float2bfloat16_rn(y);
    __nv_bfloat16 lx = __float2bfloat16_rn(x - __bfloat162float(hx));
    __nv_bfloat16 ly = __float2bfloat16_rn(y - __bfloat162float(hy));
    hi = (uint32_t)__bfloat16_as_ushort(hx) | ((uint32_t)__bfloat16_as_ushort(hy) << 16);
    lo = (uint32_t)__bfloat16_as_ushort(lx) | ((uint32_t)__bfloat16_as_ushort(ly) << 16);
}

// ============================ bf16-split tensor GEMM ============================
// C tile = 128 rows x 152 cols per CTA; grid = (M/128, 2 n-halves); 4 warps.
__global__ __launch_bounds__(128, 2) void gemm_tc(
    const float* __restrict__ A,
    const __nv_bfloat16* __restrict__ Whi, const __nv_bfloat16* __restrict__ Wlo,
    const float* __restrict__ biasp, float* __restrict__ C,
    float* __restrict__ C2, int lda, int Kact, int kchunks, int doRelu)
{
    extern __shared__ char smem[];
    const uint32_t sb = smem_u32(smem);
    const int tid  = threadIdx.x;
    const int wid  = tid >> 5;         // m quarter (32 rows)
    const int lane = tid & 31;
    const size_t rowBase = (size_t)blockIdx.x * 128;
    const int nBase = blockIdx.y * 152;   // n-half origin (global col)
    const int Kp = kchunks * 32;
    // last chunk covers <=16 real k values -> skip its second k-step
    const bool skipKs1 = (Kact - (kchunks - 1) * 32) <= 16;

    // ldmatrix per-lane offsets
    const int lr = lane & 7;
    const int g  = lane >> 3;
    const uint32_t aoff = ((uint32_t)(wid * 32 + lr + (g & 1) * 8)) * ROWB + ((g >> 1) << 4);
    const uint32_t boff = ((uint32_t)(lr + (g >> 1) * 8)) * ROWB + ((g & 1) << 4);
    const uint32_t boff2 = ((uint32_t)(144 + lr)) * ROWB + ((g & 1) << 4);

    float acc[2][19][4];
#pragma unroll
    for (int i = 0; i < 2; i++)
#pragma unroll
        for (int j = 0; j < 19; j++)
#pragma unroll
            for (int q = 0; q < 4; q++) acc[i][j][q] = 0.f;

    float4 pre[8];
    auto ldg_regs = [&](int cidx) {
        const int k0 = cidx * 32;
#pragma unroll
        for (int i = 0; i < 8; ++i) {
            const int flat = tid + (i << 7);
            const int r = flat >> 3;
            const int j = flat & 7;
            const int k = k0 + (j << 2);
            pre[i] = (k < Kact) ? *(const float4*)(A + (rowBase + r) * lda + k)
                                : make_float4(0.f, 0.f, 0.f, 0.f);
        }
    };
    auto sts_regs = [&](int cidx) {
        char* base = smem + (cidx & 1) * BUFSTRIDE;
#pragma unroll
        for (int i = 0; i < 8; ++i) {
            const int flat = tid + (i << 7);
            const int r = flat >> 3;
            const int j = flat & 7;
            uint2 hi, lo;
            split_pack(pre[i].x, pre[i].y, hi.x, lo.x);
            split_pack(pre[i].z, pre[i].w, hi.y, lo.y);
            const uint32_t o = (uint32_t)r * ROWB + j * 8;
            *(uint2*)(base + A_HI_OFF + o) = hi;
            *(uint2*)(base + A_LO_OFF + o) = lo;
        }
    };
    auto cp_B = [&](int cidx) {
        const uint32_t base = sb + (cidx & 1) * BUFSTRIDE;
        const int k0 = cidx * 32;
#pragma unroll
        for (int i = 0; i < 10; ++i) {
            const int flat = tid + (i << 7);
            if (flat < 1216) {
                const int j = flat & 3;                 // 16B chunk within row
                const int idx = flat >> 2;              // 0..303
                const int isLo = idx >= 152;
                const int n = isLo ? idx - 152 : idx;
                const __nv_bfloat16* src =
                    (isLo ? Wlo : Whi) + (size_t)(nBase + n) * Kp + k0 + j * 8;
                const uint32_t dst = base + (isLo ? B_LO_OFF : B_HI_OFF)
                                   + (uint32_t)n * ROWB + j * 16;
                cp16(dst, src);
            }
        }
        CP_COMMIT();
    };

    // prologue
    ldg_regs(0);
    sts_regs(0);
    cp_B(0);
    if (kchunks > 1) { cp_B(1); ldg_regs(1); }

    for (int c = 0; c < kchunks; ++c) {
        if (c + 1 < kchunks) asm volatile("cp.async.wait_group 1;" ::: "memory");
        else                 asm volatile("cp.async.wait_group 0;" ::: "memory");
        __syncthreads();

        if (c + 1 < kchunks) sts_regs(c + 1);
        if (c + 2 < kchunks) ldg_regs(c + 2);

        const uint32_t base = sb + (c & 1) * BUFSTRIDE;
#pragma unroll
        for (int ks = 0; ks < 2; ++ks) {
            if (ks == 1 && skipKs1 && c == kchunks - 1) continue;
            const uint32_t kb = ks << 5;   // 16 bf16 = 32 bytes
            uint32_t ah[2][4], al[2][4];
#pragma unroll
            for (int mt = 0; mt < 2; ++mt) {
                const uint32_t ao = aoff + mt * (16 * ROWB) + kb;
                LDSM4(ah[mt], base + A_HI_OFF + ao);
                LDSM4(al[mt], base + A_LO_OFF + ao);
            }
#pragma unroll
            for (int ntp = 0; ntp < 9; ++ntp) {
                uint32_t bh[4], bl[4];
                const uint32_t bo = boff + (uint32_t)ntp * (16 * ROWB) + kb;
                LDSM4(bh, base + B_HI_OFF + bo);
                LDSM4(bl, base + B_LO_OFF + bo);
                // term-major ordering: same-acc reuse distance = 4 MMAs
#pragma unroll
                for (int mt = 0; mt < 2; ++mt) {
                    MMAB(acc[mt][2 * ntp],     al[mt], bh[0], bh[1]);
                    MMAB(acc[mt][2 * ntp + 1], al[mt], bh[2], bh[3]);
                }
#pragma unroll
                for (int mt = 0; mt < 2; ++mt) {
                    MMAB(acc[mt][2 * ntp],     ah[mt], bl[0], bl[1]);
                    MMAB(acc[mt][2 * ntp + 1], ah[mt], bl[2], bl[3]);
                }
#pragma unroll
                for (int mt = 0; mt < 2; ++mt) {
                    MMAB(acc[mt][2 * ntp],     ah[mt], bh[0], bh[1]);
                    MMAB(acc[mt][2 * ntp + 1], ah[mt], bh[2], bh[3]);
                }
            }
            uint32_t b2h[2], b2l[2];
            LDSM2(b2h, base + B_HI_OFF + boff2 + kb);
            LDSM2(b2l, base + B_LO_OFF + boff2 + kb);
#pragma unroll
            for (int mt = 0; mt < 2; ++mt)
                MMAB(acc[mt][18], al[mt], b2h[0], b2h[1]);
#pragma unroll
            for (int mt = 0; mt < 2; ++mt)
                MMAB(acc[mt][18], ah[mt], b2l[0], b2l[1]);
#pragma unroll
            for (int mt = 0; mt < 2; ++mt)
                MMAB(acc[mt][18], ah[mt], b2h[0], b2h[1]);
        }
        __syncthreads();
        if (c + 2 < kchunks) cp_B(c + 2);
    }

    // ---------- epilogue: bias + relu, direct float2 stores ----------
    const int colq = (lane & 3) * 2;
    const int rquad = lane >> 2;
#pragma unroll
    for (int mt = 0; mt < 2; ++mt) {
        const size_t row0 = rowBase + wid * 32 + mt * 16 + rquad;
#pragma unroll
        for (int nt = 0; nt < 19; ++nt) {
            const int col = nBase + nt * 8 + colq;
            const float2 bv = *(const float2*)(biasp + col);
            float2 v01, v23;
            v01.x = acc[mt][nt][0] + bv.x;
            v01.y = acc[mt][nt][1] + bv.y;
            v23.x = acc[mt][nt][2] + bv.x;
            v23.y = acc[mt][nt][3] + bv.y;
            if (doRelu) {
                v01.x = fmaxf(v01.x, 0.f); v01.y = fmaxf(v01.y, 0.f);
                v23.x = fmaxf(v23.x, 0.f); v23.y = fmaxf(v23.y, 0.f);
            }
            const size_t o0 = row0 * NP + col;
            const size_t o1 = (row0 + 8) * NP + col;
            *(float2*)(C + o0) = v01;
            *(float2*)(C + o1) = v23;
            if (C2) {
                *(float2*)(C2 + o0) = v01;
                *(float2*)(C2 + o1) = v23;
            }
        }
    }
}

// ============ fused prepack: all weights (transpose+pad+bf16 split) + biases ============
#define SZ_N (NP * 64)
#define SZ_E (NP * 32)
#define SZ_M (NP * 320)
#define PACK_TOTAL (SZ_N + SZ_E + 6 * SZ_M + 8 * NP)

__global__ __launch_bounds__(256) void pack_all_kernel(
    const float* __restrict__ Wn, const float* __restrict__ We,
    const float* __restrict__ W1, const float* __restrict__ W2,
    const float* __restrict__ bn, const float* __restrict__ be,
    const float* __restrict__ b1, const float* __restrict__ b2)
{
    int idx = blockIdx.x * 256 + threadIdx.x;
    if (idx >= PACK_TOTAL) return;

    const float* W; __nv_bfloat16 *Whi, *Wlo; int Kin, Kp;
    if (idx < SZ_N) {
        W = Wn; Whi = g_Wnhi; Wlo = g_Wnlo; Kin = NODE_IN; Kp = 64;
    } else if ((idx -= SZ_N) < SZ_E) {
        W = We; Whi = g_Wehi; Wlo = g_Welo; Kin = EDGE_IN; Kp = 32;
    } else if ((idx -= SZ_E) < 3 * SZ_M) {
        const int l = idx / SZ_M; idx -= l * SZ_M;
        W = W1 + (size_t)l * HH * HH;
        Whi = g_W1hi + (size_t)l * SZ_M; Wlo = g_W1lo + (size_t)l * SZ_M;
        Kin = HH; Kp = 320;
    } else if ((idx -= 3 * SZ_M) < 3 * SZ_M) {
        const int l = idx / SZ_M; idx -= l * SZ_M;
        W = W2 + (size_t)l * HH * HH;
        Whi = g_W2hi + (size_t)l * SZ_M; Wlo = g_W2lo + (size_t)l * SZ_M;
        Kin = HH; Kp = 320;
    } else {
        idx -= 3 * SZ_M;
        const int which = idx / NP;       // 0:bn 1:be 2..4:b1 5..7:b2
        const int n = idx - which * NP;
        const float* src = (which == 0) ? bn
                         : (which == 1) ? be
                         : (which < 5)  ? b1 + (size_t)(which - 2) * HH
                                        : b2 + (size_t)(which - 5) * HH;
        g_biasp[idx] = (n < HH) ? src[n] : 0.f;
        return;
    }
    const int n = idx / Kp;
    const int k = idx - n * Kp;
    float v = 0.f;
    if (k < Kin && n < HH) v = W[(size_t)k * HH + n];
    __nv_bfloat16 h = __float2bfloat16_rn(v);
    Whi[idx] = h;
    Wlo[idx] = __float2bfloat16_rn(v - __bfloat162float(h));
}

// ============ message: z[dst] += relu(h[src] + ef), thread = edge x 8 cols ============
__global__ __launch_bounds__(256) void message_kernel(
    const float* __restrict__ h, const float* __restrict__ ef,
    const int* __restrict__ src, const int* __restrict__ dst,
    float* __restrict__ z)
{
    const int idx = blockIdx.x * blockDim.x + threadIdx.x;
    if (idx >= NE * 38) return;
    const int e = idx / 38;
    const int q = (idx - e * 38) << 3;
    const int s = __ldg(src + e);
    const int d = __ldg(dst + e);
    const float4* hp = (const float4*)(h + (size_t)s * NP + q);
    const float4* ep = (const float4*)(ef + (size_t)e * NP + q);
    const float4 h0 = hp[0], h1 = hp[1];
    const float4 e0 = ep[0], e1 = ep[1];
    float* zp = z + (size_t)d * NP + q;
    float m;
    m = h0.x + e0.x; if (m > 0.f) atomicAdd(zp + 0, m);
    m = h0.y + e0.y; if (m > 0.f) atomicAdd(zp + 1, m);
    m = h0.z + e0.z; if (m > 0.f) atomicAdd(zp + 2, m);
    m = h0.w + e0.w; if (m > 0.f) atomicAdd(zp + 3, m);
    m = h1.x + e1.x; if (m > 0.f) atomicAdd(zp + 4, m);
    m = h1.y + e1.y; if (m > 0.f) atomicAdd(zp + 5, m);
    m = h1.z + e1.z; if (m > 0.f) atomicAdd(zp + 6, m);
    m = h1.w + e1.w; if (m > 0.f) atomicAdd(zp + 7, m);
}

// ============ pool: out[seg[n]] += h[n] — run-compressed atomics ============
// warp = 32 consecutive nodes (sorted seg -> long runs), lane = one column.
// grid: (NN/32/8, 10 col-groups), block 256 (8 warps).
__global__ __launch_bounds__(256) void pool_kernel(
    const float* __restrict__ h, const int* __restrict__ seg,
    float* __restrict__ out)
{
    const int wid  = threadIdx.x >> 5;
    const int lane = threadIdx.x & 31;
    const int n0   = (blockIdx.x * 8 + wid) * 32;
    const int col  = blockIdx.y * 32 + lane;
    const bool act = col < HH;

    float v[32];
    int   sg[32];
#pragma unroll
    for (int i = 0; i < 32; ++i) {
        v[i]  = act ? __ldg(h + (size_t)(n0 + i) * NP + col) : 0.f;
        sg[i] = __ldg(seg + n0 + i);
    }
    float acc = 0.f;
#pragma unroll
    for (int i = 0; i < 32; ++i) {
        acc += v[i];
        const bool flush = (i == 31) || (sg[i + 1 > 31 ? 31 : i + 1] != sg[i]) || (i == 31);
        if ((i == 31) || (sg[i + 1 <= 31 ? i + 1 : 31] != sg[i])) {
            if (act) atomicAdd(out + (size_t)sg[i] * HH + col, acc);
            acc = 0.f;
        }
        (void)flush;
    }
}

__global__ __launch_bounds__(256) void zero_kernel(float* __restrict__ p, int n)
{
    const int idx = blockIdx.x * blockDim.x + threadIdx.x;
    if (idx < n) p[idx] = 0.f;
}

__global__ __launch_bounds__(256) void diff_kernel(float* __restrict__ out)
{
    const int idx = blockIdx.x * blockDim.x + threadIdx.x;
    const int BH = BB * HH;
    if (idx < BH) out[idx] = out[BH + idx] - out[2 * BH + idx];
}

// ============================== host orchestration ==============================
static void run_gin(const float* x, const float* e,
                    const int* src, const int* dst, const int* seg,
                    __nv_bfloat16* Wnhi, __nv_bfloat16* Wnlo,
                    __nv_bfloat16* Wehi, __nv_bfloat16* Welo,
                    __nv_bfloat16* W1hi, __nv_bfloat16* W1lo,
                    __nv_bfloat16* W2hi, __nv_bfloat16* W2lo,
                    float* biasp,
                    float* h, float* ef, float* z, float* t,
                    float* outPart)
{
    const dim3 gN(NN / 128, 2);
    const dim3 gE(NE / 128, 2);

    // node proj: h = relu(x @ Wn + bn), dual-write z = h (layer 0 input)
    gemm_tc<<<gN, 128, SMEM_BYTES>>>(x, Wnhi, Wnlo, biasp, h, z,
                                     NODE_IN, NODE_IN, 2, 1);
    // edge proj: ef = e @ We + be
    gemm_tc<<<gE, 128, SMEM_BYTES>>>(e, Wehi, Welo, biasp + NP, ef, nullptr,
                                     EDGE_IN, EDGE_IN, 1, 0);

    for (int l = 0; l < 3; l++) {
        message_kernel<<<(NE * 38 + 255) / 256, 256>>>(h, ef, src, dst, z);
        gemm_tc<<<gN, 128, SMEM_BYTES>>>(
            z, W1hi + (size_t)l * NP * 320, W1lo + (size_t)l * NP * 320,
            biasp + (size_t)(2 + l) * NP, t, nullptr, NP, NP, 10, 1);
        gemm_tc<<<gN, 128, SMEM_BYTES>>>(
            t, W2hi + (size_t)l * NP * 320, W2lo + (size_t)l * NP * 320,
            biasp + (size_t)(5 + l) * NP, h, (l < 2) ? z : nullptr,
            NP, NP, 10, (l < 2) ? 1 : 0);
    }
    const dim3 gP(NN / 32 / 8, 10);
    pool_kernel<<<gP, 256>>>(h, seg, outPart);
}

extern "C" void kernel_launch(void* const* d_in, const int* in_sizes, int n_in,
                              void* d_out, int out_size)
{
    const float* r_x = (const float*)d_in[0];
    const float* r_e = (const float*)d_in[1];
    const float* p_x = (const float*)d_in[2];
    const float* p_e = (const float*)d_in[3];
    const float* Wn  = (const float*)d_in[4];
    const float* bn  = (const float*)d_in[5];
    const float* We  = (const float*)d_in[6];
    const float* be  = (const float*)d_in[7];
    const float* W1  = (const float*)d_in[8];
    const float* b1  = (const float*)d_in[9];
    const float* W2  = (const float*)d_in[10];
    const float* b2  = (const float*)d_in[11];
    const int* r_src = (const int*)d_in[12];
    const int* r_dst = (const int*)d_in[13];
    const int* r_seg = (const int*)d_in[14];
    const int* p_src = (const int*)d_in[15];
    const int* p_dst = (const int*)d_in[16];
    const int* p_seg = (const int*)d_in[17];

    float* out   = (float*)d_out;
    float* r_sum = out + (size_t)BB * HH;
    float* p_sum = out + (size_t)2 * BB * HH;

    float *h, *ef, *z, *t, *biasp;
    __nv_bfloat16 *Wnhi, *Wnlo, *Wehi, *Welo, *W1hi, *W1lo, *W2hi, *W2lo;
    cudaGetSymbolAddress((void**)&h,    g_h);
    cudaGetSymbolAddress((void**)&ef,   g_ef);
    cudaGetSymbolAddress((void**)&z,    g_z);
    cudaGetSymbolAddress((void**)&t,    g_t);
    cudaGetSymbolAddress((void**)&Wnhi, g_Wnhi);
    cudaGetSymbolAddress((void**)&Wnlo, g_Wnlo);
    cudaGetSymbolAddress((void**)&Wehi, g_Wehi);
    cudaGetSymbolAddress((void**)&Welo, g_Welo);
    cudaGetSymbolAddress((void**)&W1hi, g_W1hi);
    cudaGetSymbolAddress((void**)&W1lo, g_W1lo);
    cudaGetSymbolAddress((void**)&W2hi, g_W2hi);
    cudaGetSymbolAddress((void**)&W2lo, g_W2lo);
    cudaGetSymbolAddress((void**)&biasp, g_biasp);

    cudaFuncSetAttribute(gemm_tc, cudaFuncAttributeMaxDynamicSharedMemorySize,
                         SMEM_BYTES);

    // launch 0: fused prepack (weights + biases)
    pack_all_kernel<<<(PACK_TOTAL + 255) / 256, 256>>>(Wn, We, W1, W2, bn, be, b1, b2);
    // launch 1: zero accumulation targets (r_sum, p_sum contiguous)
    zero_kernel<<<(2 * BB * HH + 255) / 256, 256>>>(r_sum, 2 * BB * HH);

    for (int g = 0; g < 2; g++) {
        run_gin(r_x + (size_t)g * NN * NODE_IN,
                r_e + (size_t)g * NE * EDGE_IN,
                r_src + (size_t)g * NE, r_dst + (size_t)g * NE,
                r_seg + (size_t)g * NN,
                Wnhi, Wnlo, Wehi, Welo, W1hi, W1lo, W2hi, W2lo, biasp,
                h, ef, z, t, r_sum);
    }
    run_gin(p_x, p_e, p_src, p_dst, p_seg,
            Wnhi, Wnlo, Wehi, Welo, W1hi, W1lo, W2hi, W2lo, biasp,
            h, ef, z, t, p_sum);

    diff_kernel<<<(BB * HH + 255) / 256, 256>>>(out);
}